// round 1
// baseline (speedup 1.0000x reference)
#include <cuda_runtime.h>
#include <math.h>

#define Nn   4096
#define Tt   2048
#define Dd   256
#define H1d  128
#define H2d  32
#define NHd  4
#define CAP  96
#define LRELU_ALPHA 0.2f

// ------------------------- scratch (__device__ globals; no allocation) -----
__device__ float g_Wh_c[NHd * Nn * Dd];     // per-head x@W (concept)
__device__ float g_Wh_t[NHd * Tt * Dd];     // per-head t_x@W (text)
__device__ float g_f_c[NHd * Nn], g_g_c[NHd * Nn];
__device__ float g_f_t[NHd * Tt], g_g_t[NHd * Tt];
__device__ int   g_nbr_c[Nn * CAP];
__device__ float g_val_c[Nn * CAP];
__device__ int   g_cnt_c[Nn];
__device__ int   g_nbr_t[Tt * CAP];
__device__ float g_val_t[Tt * CAP];
__device__ int   g_cnt_t[Tt];
__device__ float g_hcat_c[Nn * NHd * Dd];   // concatenated GAT heads (concept)
__device__ float g_hcat_t[Tt * NHd * Dd];
__device__ float g_concept[Nn * Dd];
__device__ float g_gtext[Tt * Dd];
__device__ float g_ctext[Nn * Dd];
__device__ float g_fused[Nn * Dd];
__device__ float g_fusion[Nn * Dd];
__device__ float g_tmp1[Nn * H1d];
__device__ float g_h1[Nn * H1d];
__device__ float g_tmp2[Nn * H2d];

// ------------------------- CSR build (deterministic ordered compaction) ----
__global__ void build_csr_kernel(const float* __restrict__ adj, int n,
                                 int* __restrict__ nbr, float* __restrict__ val,
                                 int* __restrict__ cnt) {
    int i = blockIdx.x;
    const float* row = adj + (size_t)i * n;
    __shared__ int s_wcnt[8];
    __shared__ int s_rc;
    int t = threadIdx.x, lane = t & 31, wid = t >> 5;
    if (t == 0) s_rc = 0;
    __syncthreads();
    for (int base = 0; base < n; base += 256) {
        float v = row[base + t];
        bool p = v > 0.0f;
        unsigned m = __ballot_sync(0xffffffffu, p);
        int pos = __popc(m & ((1u << lane) - 1u));
        if (lane == 0) s_wcnt[wid] = __popc(m);
        __syncthreads();
        int off = s_rc;
        #pragma unroll
        for (int w = 0; w < 8; w++) if (w < wid) off += s_wcnt[w];
        if (p) {
            int o = off + pos;
            if (o < CAP) { nbr[i * CAP + o] = base + t; val[i * CAP + o] = v; }
        }
        __syncthreads();
        if (t == 0) {
            int tot = 0;
            #pragma unroll
            for (int w = 0; w < 8; w++) tot += s_wcnt[w];
            s_rc += tot;
        }
        __syncthreads();
    }
    if (t == 0) cnt[i] = min(s_rc, CAP);
}

// ------------------------- tiled fp32 SGEMM  (C = A@B [+bias]) -------------
// A: [M,K] row-major (TA=false) or [K,M] row-major interpreted as A^T (TA=true)
// B: [K,N] row-major.  M multiple of 64, K multiple of 16. N arbitrary.
template <bool TA>
__global__ void sgemm_kernel(const float* __restrict__ A, const float* __restrict__ B,
                             const float* __restrict__ bias, float* __restrict__ C,
                             int M, int N, int K) {
    __shared__ __align__(16) float As[16][64];
    __shared__ __align__(16) float Bs[16][64];
    int bm = blockIdx.y * 64;
    int bn = blockIdx.x * 64;
    int t = threadIdx.x;
    int tx = t & 15, ty = t >> 4;
    float acc[4][4] = {};
    for (int k0 = 0; k0 < K; k0 += 16) {
        #pragma unroll
        for (int j = 0; j < 4; j++) {
            int li = t + j * 256;
            float av;
            if (TA) {
                int r = li & 63, c = li >> 6;
                av = A[(size_t)(k0 + c) * M + bm + r];
                As[c][r] = av;
            } else {
                int r = li >> 4, c = li & 15;
                av = A[(size_t)(bm + r) * K + k0 + c];
                As[c][r] = av;
            }
            int rb = li >> 6, cb = li & 63;
            float bv = 0.0f;
            if (bn + cb < N) bv = B[(size_t)(k0 + rb) * N + bn + cb];
            Bs[rb][cb] = bv;
        }
        __syncthreads();
        #pragma unroll
        for (int k = 0; k < 16; k++) {
            float4 a4 = *reinterpret_cast<const float4*>(&As[k][ty << 2]);
            float4 b4 = *reinterpret_cast<const float4*>(&Bs[k][tx << 2]);
            float a[4] = {a4.x, a4.y, a4.z, a4.w};
            float b[4] = {b4.x, b4.y, b4.z, b4.w};
            #pragma unroll
            for (int u = 0; u < 4; u++)
                #pragma unroll
                for (int v = 0; v < 4; v++)
                    acc[u][v] += a[u] * b[v];
        }
        __syncthreads();
    }
    #pragma unroll
    for (int u = 0; u < 4; u++) {
        int row = bm + (ty << 2) + u;
        #pragma unroll
        for (int v = 0; v < 4; v++) {
            int col = bn + (tx << 2) + v;
            if (col < N) {
                float r = acc[u][v];
                if (bias) r += bias[col];
                C[(size_t)row * N + col] = r;
            }
        }
    }
}

// ------------------------- f/g projections (one warp per (h,n)) ------------
__global__ void fg_kernel(const float* __restrict__ Wh, const float* __restrict__ asrc,
                          const float* __restrict__ adst, float* __restrict__ f,
                          float* __restrict__ g, int n) {
    int gw = (blockIdx.x * blockDim.x + threadIdx.x) >> 5;
    int lane = threadIdx.x & 31;
    if (gw >= NHd * n) return;
    int h = gw / n, i = gw - h * n;
    const float* w  = Wh + ((size_t)h * n + i) * Dd;
    const float* as = asrc + h * Dd;
    const float* ad = adst + h * Dd;
    float accf = 0.0f, accg = 0.0f;
    #pragma unroll
    for (int c = 0; c < Dd / 32; c++) {
        float v = w[lane + 32 * c];
        accf += v * as[lane + 32 * c];
        accg += v * ad[lane + 32 * c];
    }
    #pragma unroll
    for (int o = 16; o; o >>= 1) {
        accf += __shfl_down_sync(0xffffffffu, accf, o);
        accg += __shfl_down_sync(0xffffffffu, accg, o);
    }
    if (lane == 0) { f[gw] = accf; g[gw] = accg; }
}

// ------------------------- sparse GAT attention + aggregation + ELU --------
// one block = one (node i, head h). 256 threads = D columns.
__global__ void gat_attn_kernel(const float* __restrict__ Wh, const float* __restrict__ f,
                                const float* __restrict__ g, const int* __restrict__ nbr,
                                const int* __restrict__ cnt, float* __restrict__ hcat, int n) {
    int i = blockIdx.x, h = blockIdx.y;
    int t = threadIdx.x;
    __shared__ int   sj[CAP];
    __shared__ float sw[CAP];
    __shared__ float s_m, s_dinv;
    int c = cnt[i];
    if (t < c) sj[t] = nbr[i * CAP + t];
    __syncthreads();
    float fi = f[h * n + i];
    if (t < c) {
        float s = fi + g[h * n + sj[t]];
        sw[t] = (s >= 0.0f) ? s : LRELU_ALPHA * s;
    }
    __syncthreads();
    if (t == 0) {
        float m = -1e30f;
        for (int k = 0; k < c; k++) m = fmaxf(m, sw[k]);
        s_m = m;
    }
    __syncthreads();
    if (t < c) sw[t] = expf(sw[t] - s_m);
    __syncthreads();
    if (t == 0) {
        float d = 0.0f;
        for (int k = 0; k < c; k++) d += sw[k];
        s_dinv = 1.0f / d;
    }
    __syncthreads();
    const float* base = Wh + (size_t)h * n * Dd;
    float acc = 0.0f;
    for (int k = 0; k < c; k++)
        acc += sw[k] * base[(size_t)sj[k] * Dd + t];
    acc *= s_dinv;
    float o = (acc > 0.0f) ? acc : expm1f(acc);
    hcat[(size_t)i * (NHd * Dd) + h * Dd + t] = o;
}

// ------------------------- gated fusion elementwise ------------------------
__global__ void fuse_kernel(const float* __restrict__ a, const float* __restrict__ b,
                            float* __restrict__ out, int total) {
    int idx = blockIdx.x * blockDim.x + threadIdx.x;
    if (idx < total) {
        float ca = a[idx], cb = b[idx];
        float z = 1.0f / (1.0f + expf(-(ca + cb)));
        out[idx] = z * ca + (1.0f - z) * cb;
    }
}

// ------------------------- sparse adj @ X (GCN), optional ReLU -------------
__global__ void spmm_kernel(const int* __restrict__ nbr, const float* __restrict__ val,
                            const int* __restrict__ cnt, const float* __restrict__ X,
                            float* __restrict__ Y, int ncols, int do_relu) {
    int i = blockIdx.x;
    int t = threadIdx.x;  // blockDim.x == ncols
    int c = cnt[i];
    float acc = 0.0f;
    for (int k = 0; k < c; k++) {
        int j = nbr[i * CAP + k];
        acc += val[i * CAP + k] * X[(size_t)j * ncols + t];
    }
    if (do_relu) acc = fmaxf(acc, 0.0f);
    Y[(size_t)i * ncols + t] = acc;
}

// ------------------------- recon = mu @ mu^T (K=32) ------------------------
__global__ void aat_kernel(const float* __restrict__ A, float* __restrict__ C, int n) {
    __shared__ __align__(16) float Ai[64][33];
    __shared__ __align__(16) float Aj[64][33];
    int bi = blockIdx.y * 64, bj = blockIdx.x * 64;
    int t = threadIdx.x;
    for (int li = t; li < 64 * 32; li += 256) {
        int r = li >> 5, c = li & 31;
        Ai[r][c] = A[(size_t)(bi + r) * H2d + c];
        Aj[r][c] = A[(size_t)(bj + r) * H2d + c];
    }
    __syncthreads();
    int tx = t & 15, ty = t >> 4;
    float acc[4][4] = {};
    #pragma unroll
    for (int k = 0; k < 32; k++) {
        float a[4], b[4];
        #pragma unroll
        for (int u = 0; u < 4; u++) { a[u] = Ai[(ty << 2) + u][k]; b[u] = Aj[(tx << 2) + u][k]; }
        #pragma unroll
        for (int u = 0; u < 4; u++)
            #pragma unroll
            for (int v = 0; v < 4; v++)
                acc[u][v] += a[u] * b[v];
    }
    #pragma unroll
    for (int u = 0; u < 4; u++)
        #pragma unroll
        for (int v = 0; v < 4; v++)
            C[(size_t)(bi + (ty << 2) + u) * n + bj + (tx << 2) + v] = acc[u][v];
}

// ------------------------- host-side launch helpers ------------------------
static inline void run_sgemm_nn(const float* A, const float* B, const float* bias,
                                float* C, int M, int N, int K) {
    dim3 grid((N + 63) / 64, M / 64);
    sgemm_kernel<false><<<grid, 256>>>(A, B, bias, C, M, N, K);
}
static inline void run_sgemm_tn(const float* A, const float* B, const float* bias,
                                float* C, int M, int N, int K) {
    dim3 grid((N + 63) / 64, M / 64);
    sgemm_kernel<true><<<grid, 256>>>(A, B, bias, C, M, N, K);
}

extern "C" void kernel_launch(void* const* d_in, const int* in_sizes, int n_in,
                              void* d_out, int out_size) {
    const float* x        = (const float*)d_in[0];
    const float* adj      = (const float*)d_in[1];
    const float* t_x      = (const float*)d_in[2];
    const float* t_adj    = (const float*)d_in[3];
    const float* tfidf    = (const float*)d_in[4];
    const float* gat_W    = (const float*)d_in[5];
    const float* gat_asrc = (const float*)d_in[6];
    const float* gat_adst = (const float*)d_in[7];
    const float* gat_fcW  = (const float*)d_in[8];
    const float* gat_fcb  = (const float*)d_in[9];
    const float* t_W      = (const float*)d_in[10];
    const float* t_asrc   = (const float*)d_in[11];
    const float* t_adst   = (const float*)d_in[12];
    const float* t_fcW    = (const float*)d_in[13];
    const float* t_fcb    = (const float*)d_in[14];
    const float* fus_W    = (const float*)d_in[15];
    const float* fus_b    = (const float*)d_in[16];
    const float* gc1_W    = (const float*)d_in[17];
    const float* gc2_W    = (const float*)d_in[18];
    const float* gc3_W    = (const float*)d_in[19];

    float* out    = (float*)d_out;
    float* mu     = out + (size_t)Nn * Nn;
    float* logvar = mu + (size_t)Nn * H2d;

    float *Wh_c, *Wh_t, *f_c, *g_c, *f_t, *g_t, *val_c, *val_t;
    float *hcat_c, *hcat_t, *concept, *gtext, *ctext, *fused, *fusion, *tmp1, *h1, *tmp2;
    int *nbr_c, *cnt_c, *nbr_t, *cnt_t;
    cudaGetSymbolAddress((void**)&Wh_c,   g_Wh_c);
    cudaGetSymbolAddress((void**)&Wh_t,   g_Wh_t);
    cudaGetSymbolAddress((void**)&f_c,    g_f_c);
    cudaGetSymbolAddress((void**)&g_c,    g_g_c);
    cudaGetSymbolAddress((void**)&f_t,    g_f_t);
    cudaGetSymbolAddress((void**)&g_t,    g_g_t);
    cudaGetSymbolAddress((void**)&nbr_c,  g_nbr_c);
    cudaGetSymbolAddress((void**)&val_c,  g_val_c);
    cudaGetSymbolAddress((void**)&cnt_c,  g_cnt_c);
    cudaGetSymbolAddress((void**)&nbr_t,  g_nbr_t);
    cudaGetSymbolAddress((void**)&val_t,  g_val_t);
    cudaGetSymbolAddress((void**)&cnt_t,  g_cnt_t);
    cudaGetSymbolAddress((void**)&hcat_c, g_hcat_c);
    cudaGetSymbolAddress((void**)&hcat_t, g_hcat_t);
    cudaGetSymbolAddress((void**)&concept,g_concept);
    cudaGetSymbolAddress((void**)&gtext,  g_gtext);
    cudaGetSymbolAddress((void**)&ctext,  g_ctext);
    cudaGetSymbolAddress((void**)&fused,  g_fused);
    cudaGetSymbolAddress((void**)&fusion, g_fusion);
    cudaGetSymbolAddress((void**)&tmp1,   g_tmp1);
    cudaGetSymbolAddress((void**)&h1,     g_h1);
    cudaGetSymbolAddress((void**)&tmp2,   g_tmp2);

    // 1) adjacency -> CSR (values kept for GCN; mask for GAT)
    build_csr_kernel<<<Nn, 256>>>(adj, Nn, nbr_c, val_c, cnt_c);
    build_csr_kernel<<<Tt, 256>>>(t_adj, Tt, nbr_t, val_t, cnt_t);

    // 2) per-head Wh = x @ W[h]
    for (int h = 0; h < NHd; h++) {
        run_sgemm_nn(x,   gat_W + (size_t)h * Dd * Dd, nullptr, Wh_c + (size_t)h * Nn * Dd, Nn, Dd, Dd);
        run_sgemm_nn(t_x, t_W   + (size_t)h * Dd * Dd, nullptr, Wh_t + (size_t)h * Tt * Dd, Tt, Dd, Dd);
    }

    // 3) attention projections f,g
    {
        int warps = NHd * Nn;
        fg_kernel<<<(warps * 32 + 255) / 256, 256>>>(Wh_c, gat_asrc, gat_adst, f_c, g_c, Nn);
        warps = NHd * Tt;
        fg_kernel<<<(warps * 32 + 255) / 256, 256>>>(Wh_t, t_asrc, t_adst, f_t, g_t, Tt);
    }

    // 4) sparse masked softmax attention + aggregation + ELU (heads concat)
    gat_attn_kernel<<<dim3(Nn, NHd), 256>>>(Wh_c, f_c, g_c, nbr_c, cnt_c, hcat_c, Nn);
    gat_attn_kernel<<<dim3(Tt, NHd), 256>>>(Wh_t, f_t, g_t, nbr_t, cnt_t, hcat_t, Tt);

    // 5) output fc per graph
    run_sgemm_nn(hcat_c, gat_fcW, gat_fcb, concept, Nn, Dd, NHd * Dd);
    run_sgemm_nn(hcat_t, t_fcW,   t_fcb,   gtext,   Tt, Dd, NHd * Dd);

    // 6) c_text = tfidf^T @ gat_text   (A^T form: A=[T,N])
    run_sgemm_tn(tfidf, gtext, nullptr, ctext, Nn, Dd, Tt);

    // 7) gated fusion + fc
    fuse_kernel<<<(Nn * Dd + 255) / 256, 256>>>(concept, ctext, fused, Nn * Dd);
    run_sgemm_nn(fused, fus_W, fus_b, fusion, Nn, Dd, Dd);

    // 8) GCN encoder
    run_sgemm_nn(fusion, gc1_W, nullptr, tmp1, Nn, H1d, Dd);
    spmm_kernel<<<Nn, H1d>>>(nbr_c, val_c, cnt_c, tmp1, h1, H1d, 1);

    run_sgemm_nn(h1, gc2_W, nullptr, tmp2, Nn, H2d, H1d);
    spmm_kernel<<<Nn, H2d>>>(nbr_c, val_c, cnt_c, tmp2, mu, H2d, 0);

    run_sgemm_nn(h1, gc3_W, nullptr, tmp2, Nn, H2d, H1d);
    spmm_kernel<<<Nn, H2d>>>(nbr_c, val_c, cnt_c, tmp2, logvar, H2d, 0);

    // 9) recon = mu @ mu^T
    aat_kernel<<<dim3(Nn / 64, Nn / 64), 256>>>(mu, out, Nn);
}

// round 3
// speedup vs baseline: 1.1110x; 1.1110x over previous
#include <cuda_runtime.h>
#include <math.h>
#include <stdint.h>

#define Nn   4096
#define Tt   2048
#define Dd   256
#define H1d  128
#define H2d  32
#define NHd  4
#define CAP  96
#define LRELU_ALPHA 0.2f

// ------------------------- scratch (__device__ globals; no allocation) -----
__device__ float g_Wh_c[NHd * Nn * Dd];
__device__ float g_Wh_t[NHd * Tt * Dd];
__device__ float g_f_c[NHd * Nn], g_g_c[NHd * Nn];
__device__ float g_f_t[NHd * Tt], g_g_t[NHd * Tt];
__device__ int   g_nbr_c[Nn * CAP];
__device__ float g_val_c[Nn * CAP];
__device__ int   g_cnt_c[Nn];
__device__ int   g_nbr_t[Tt * CAP];
__device__ float g_val_t[Tt * CAP];
__device__ int   g_cnt_t[Tt];
__device__ float g_hcat_c[Nn * NHd * Dd];
__device__ float g_hcat_t[Tt * NHd * Dd];
__device__ float g_concept[Nn * Dd];
__device__ float g_gtext[Tt * Dd];
__device__ float g_ctext[Nn * Dd];
__device__ float g_fused[Nn * Dd];
__device__ float g_fusion[Nn * Dd];
__device__ float g_tmp1[Nn * H1d];
__device__ float g_h1[Nn * H1d];
__device__ float g_tmp2[Nn * H2d];

// ------------------------- CSR build (deterministic ordered compaction) ----
__global__ void build_csr_kernel(const float* __restrict__ adj, int n,
                                 int* __restrict__ nbr, float* __restrict__ val,
                                 int* __restrict__ cnt) {
    int i = blockIdx.x;
    const float* row = adj + (size_t)i * n;
    __shared__ int s_wcnt[8];
    __shared__ int s_rc;
    int t = threadIdx.x, lane = t & 31, wid = t >> 5;
    if (t == 0) s_rc = 0;
    __syncthreads();
    for (int base = 0; base < n; base += 256) {
        float v = row[base + t];
        bool p = v > 0.0f;
        unsigned m = __ballot_sync(0xffffffffu, p);
        int pos = __popc(m & ((1u << lane) - 1u));
        if (lane == 0) s_wcnt[wid] = __popc(m);
        __syncthreads();
        int off = s_rc;
        #pragma unroll
        for (int w = 0; w < 8; w++) if (w < wid) off += s_wcnt[w];
        if (p) {
            int o = off + pos;
            if (o < CAP) { nbr[i * CAP + o] = base + t; val[i * CAP + o] = v; }
        }
        __syncthreads();
        if (t == 0) {
            int tot = 0;
            #pragma unroll
            for (int w = 0; w < 8; w++) tot += s_wcnt[w];
            s_rc += tot;
        }
        __syncthreads();
    }
    if (t == 0) cnt[i] = min(s_rc, CAP);
}

// ------------------------- tf32 split helper -------------------------------
__device__ __forceinline__ void tf32_split(float v, float& hi, float& lo) {
    uint32_t h, l;
    asm("cvt.rna.tf32.f32 %0, %1;" : "=r"(h) : "f"(v));
    float hf = __uint_as_float(h);
    float r = v - hf;
    asm("cvt.rna.tf32.f32 %0, %1;" : "=r"(l) : "f"(r));
    hi = hf; lo = __uint_as_float(l);
}

#define MMA_TF32(c, a, b)                                                         \
    asm volatile(                                                                  \
        "mma.sync.aligned.m16n8k8.row.col.f32.tf32.tf32.f32 "                      \
        "{%0,%1,%2,%3},{%4,%5,%6,%7},{%8,%9},{%0,%1,%2,%3};"                       \
        : "+f"((c)[0]), "+f"((c)[1]), "+f"((c)[2]), "+f"((c)[3])                   \
        : "r"((a)[0]), "r"((a)[1]), "r"((a)[2]), "r"((a)[3]),                      \
          "r"((b)[0]), "r"((b)[1]))

// ------------------------- tensor-core 3xTF32 GEMM -------------------------
// C = op(A) @ op(B) [+ bias], fp32 in/out, ~fp32 accuracy via 3xTF32.
// op(A): TA ? A is [K,M] row-major : A is [M,K] row-major
// op(B): TB ? B is [N,K] row-major : B is [K,N] row-major
// Requires: M % 128 == 0, N % 64 == 0, K % 16 == 0. Batched over blockIdx.z.
#define BMt 128
#define BNt 64
#define BKt 16

template <bool TA, bool TB>
__global__ void __launch_bounds__(256) mma_gemm_kernel(
    const float* __restrict__ A, const float* __restrict__ B,
    const float* __restrict__ bias, float* __restrict__ C,
    int M, int N, int K, size_t sA, size_t sB, size_t sC) {
    __shared__ float As_hi[BKt][BMt + 4], As_lo[BKt][BMt + 4];
    __shared__ float Bs_hi[BKt][BNt + 4], Bs_lo[BKt][BNt + 4];
    const float* Ab = A + (size_t)blockIdx.z * sA;
    const float* Bb = B + (size_t)blockIdx.z * sB;
    float* Cb = C + (size_t)blockIdx.z * sC;
    int bm = blockIdx.y * BMt, bn = blockIdx.x * BNt;
    int t = threadIdx.x, lane = t & 31, w = t >> 5;
    int wm = (w & 3) * 32, wn = (w >> 2) * 32;
    int gid = lane >> 2, tig = lane & 3;

    float acc[2][4][4] = {};

    for (int k0 = 0; k0 < K; k0 += BKt) {
        // ---- load A tile into (k-major, hi/lo) smem ----
        if (!TA) {
            #pragma unroll
            for (int r = 0; r < 2; r++) {
                int row = (t >> 2) + r * 64;
                int col = (t & 3) * 4;
                float4 v = *reinterpret_cast<const float4*>(
                    Ab + (size_t)(bm + row) * K + k0 + col);
                float hi, lo;
                tf32_split(v.x, hi, lo); As_hi[col + 0][row] = hi; As_lo[col + 0][row] = lo;
                tf32_split(v.y, hi, lo); As_hi[col + 1][row] = hi; As_lo[col + 1][row] = lo;
                tf32_split(v.z, hi, lo); As_hi[col + 2][row] = hi; As_lo[col + 2][row] = lo;
                tf32_split(v.w, hi, lo); As_hi[col + 3][row] = hi; As_lo[col + 3][row] = lo;
            }
        } else {
            #pragma unroll
            for (int j = 0; j < 2; j++) {
                int idx = t + j * 256;            // float4 index, 0..511
                int row = idx >> 5;               // k 0..15
                int col = (idx & 31) * 4;         // m 0..124
                float4 v = *reinterpret_cast<const float4*>(
                    Ab + (size_t)(k0 + row) * M + bm + col);
                float hi, lo;
                tf32_split(v.x, hi, lo); As_hi[row][col + 0] = hi; As_lo[row][col + 0] = lo;
                tf32_split(v.y, hi, lo); As_hi[row][col + 1] = hi; As_lo[row][col + 1] = lo;
                tf32_split(v.z, hi, lo); As_hi[row][col + 2] = hi; As_lo[row][col + 2] = lo;
                tf32_split(v.w, hi, lo); As_hi[row][col + 3] = hi; As_lo[row][col + 3] = lo;
            }
        }
        // ---- load B tile ----
        if (!TB) {
            int row = t >> 4;                     // k 0..15
            int col = (t & 15) * 4;               // n 0..60
            float4 v = *reinterpret_cast<const float4*>(
                Bb + (size_t)(k0 + row) * N + bn + col);
            float hi, lo;
            tf32_split(v.x, hi, lo); Bs_hi[row][col + 0] = hi; Bs_lo[row][col + 0] = lo;
            tf32_split(v.y, hi, lo); Bs_hi[row][col + 1] = hi; Bs_lo[row][col + 1] = lo;
            tf32_split(v.z, hi, lo); Bs_hi[row][col + 2] = hi; Bs_lo[row][col + 2] = lo;
            tf32_split(v.w, hi, lo); Bs_hi[row][col + 3] = hi; Bs_lo[row][col + 3] = lo;
        } else {
            int row = t >> 2;                     // n 0..63
            int col = (t & 3) * 4;                // k 0..12
            float4 v = *reinterpret_cast<const float4*>(
                Bb + (size_t)(bn + row) * K + k0 + col);
            float hi, lo;
            tf32_split(v.x, hi, lo); Bs_hi[col + 0][row] = hi; Bs_lo[col + 0][row] = lo;
            tf32_split(v.y, hi, lo); Bs_hi[col + 1][row] = hi; Bs_lo[col + 1][row] = lo;
            tf32_split(v.z, hi, lo); Bs_hi[col + 2][row] = hi; Bs_lo[col + 2][row] = lo;
            tf32_split(v.w, hi, lo); Bs_hi[col + 3][row] = hi; Bs_lo[col + 3][row] = lo;
        }
        __syncthreads();

        #pragma unroll
        for (int kk = 0; kk < BKt; kk += 8) {
            uint32_t ah[2][4], al[2][4], bh[4][2], bl[4][2];
            #pragma unroll
            for (int mt = 0; mt < 2; mt++) {
                int m0 = wm + mt * 16 + gid;
                ah[mt][0] = __float_as_uint(As_hi[kk + tig][m0]);
                ah[mt][1] = __float_as_uint(As_hi[kk + tig][m0 + 8]);
                ah[mt][2] = __float_as_uint(As_hi[kk + tig + 4][m0]);
                ah[mt][3] = __float_as_uint(As_hi[kk + tig + 4][m0 + 8]);
                al[mt][0] = __float_as_uint(As_lo[kk + tig][m0]);
                al[mt][1] = __float_as_uint(As_lo[kk + tig][m0 + 8]);
                al[mt][2] = __float_as_uint(As_lo[kk + tig + 4][m0]);
                al[mt][3] = __float_as_uint(As_lo[kk + tig + 4][m0 + 8]);
            }
            #pragma unroll
            for (int nt = 0; nt < 4; nt++) {
                int n0 = wn + nt * 8 + gid;
                bh[nt][0] = __float_as_uint(Bs_hi[kk + tig][n0]);
                bh[nt][1] = __float_as_uint(Bs_hi[kk + tig + 4][n0]);
                bl[nt][0] = __float_as_uint(Bs_lo[kk + tig][n0]);
                bl[nt][1] = __float_as_uint(Bs_lo[kk + tig + 4][n0]);
            }
            #pragma unroll
            for (int mt = 0; mt < 2; mt++)
                #pragma unroll
                for (int nt = 0; nt < 4; nt++) {
                    MMA_TF32(acc[mt][nt], al[mt], bh[nt]);
                    MMA_TF32(acc[mt][nt], ah[mt], bl[nt]);
                    MMA_TF32(acc[mt][nt], ah[mt], bh[nt]);
                }
        }
        __syncthreads();
    }

    // ---- epilogue ----
    #pragma unroll
    for (int mt = 0; mt < 2; mt++) {
        int row0 = bm + wm + mt * 16 + gid;
        #pragma unroll
        for (int nt = 0; nt < 4; nt++) {
            int col = bn + wn + nt * 8 + tig * 2;
            float bx = bias ? bias[col] : 0.0f;
            float by = bias ? bias[col + 1] : 0.0f;
            *reinterpret_cast<float2*>(&Cb[(size_t)row0 * N + col]) =
                make_float2(acc[mt][nt][0] + bx, acc[mt][nt][1] + by);
            *reinterpret_cast<float2*>(&Cb[(size_t)(row0 + 8) * N + col]) =
                make_float2(acc[mt][nt][2] + bx, acc[mt][nt][3] + by);
        }
    }
}

// ------------------------- small SIMT SGEMM (N=32 cases) -------------------
__global__ void sgemm_small_kernel(const float* __restrict__ A, const float* __restrict__ B,
                                   float* __restrict__ C, int M, int N, int K) {
    __shared__ __align__(16) float As[16][64];
    __shared__ __align__(16) float Bs[16][64];
    int bm = blockIdx.y * 64;
    int bn = blockIdx.x * 64;
    int t = threadIdx.x;
    int tx = t & 15, ty = t >> 4;
    float acc[4][4] = {};
    for (int k0 = 0; k0 < K; k0 += 16) {
        #pragma unroll
        for (int j = 0; j < 4; j++) {
            int li = t + j * 256;
            int r = li >> 4, c = li & 15;
            As[c][r] = A[(size_t)(bm + r) * K + k0 + c];
            int rb = li >> 6, cb = li & 63;
            float bv = 0.0f;
            if (bn + cb < N) bv = B[(size_t)(k0 + rb) * N + bn + cb];
            Bs[rb][cb] = bv;
        }
        __syncthreads();
        #pragma unroll
        for (int k = 0; k < 16; k++) {
            float4 a4 = *reinterpret_cast<const float4*>(&As[k][ty << 2]);
            float4 b4 = *reinterpret_cast<const float4*>(&Bs[k][tx << 2]);
            float a[4] = {a4.x, a4.y, a4.z, a4.w};
            float b[4] = {b4.x, b4.y, b4.z, b4.w};
            #pragma unroll
            for (int u = 0; u < 4; u++)
                #pragma unroll
                for (int v = 0; v < 4; v++)
                    acc[u][v] += a[u] * b[v];
        }
        __syncthreads();
    }
    #pragma unroll
    for (int u = 0; u < 4; u++) {
        int row = bm + (ty << 2) + u;
        #pragma unroll
        for (int v = 0; v < 4; v++) {
            int col = bn + (tx << 2) + v;
            if (col < N) C[(size_t)row * N + col] = acc[u][v];
        }
    }
}

// ------------------------- f/g projections (one warp per (h,n)) ------------
__global__ void fg_kernel(const float* __restrict__ Wh, const float* __restrict__ asrc,
                          const float* __restrict__ adst, float* __restrict__ f,
                          float* __restrict__ g, int n) {
    int gw = (blockIdx.x * blockDim.x + threadIdx.x) >> 5;
    int lane = threadIdx.x & 31;
    if (gw >= NHd * n) return;
    int h = gw / n, i = gw - h * n;
    const float* w  = Wh + ((size_t)h * n + i) * Dd;
    const float* as = asrc + h * Dd;
    const float* ad = adst + h * Dd;
    float accf = 0.0f, accg = 0.0f;
    #pragma unroll
    for (int c = 0; c < Dd / 32; c++) {
        float v = w[lane + 32 * c];
        accf += v * as[lane + 32 * c];
        accg += v * ad[lane + 32 * c];
    }
    #pragma unroll
    for (int o = 16; o; o >>= 1) {
        accf += __shfl_down_sync(0xffffffffu, accf, o);
        accg += __shfl_down_sync(0xffffffffu, accg, o);
    }
    if (lane == 0) { f[gw] = accf; g[gw] = accg; }
}

// ------------------------- sparse GAT attention + aggregation + ELU --------
__global__ void gat_attn_kernel(const float* __restrict__ Wh, const float* __restrict__ f,
                                const float* __restrict__ g, const int* __restrict__ nbr,
                                const int* __restrict__ cnt, float* __restrict__ hcat, int n) {
    int i = blockIdx.x, h = blockIdx.y;
    int t = threadIdx.x;
    __shared__ int   sj[CAP];
    __shared__ float sw[CAP];
    __shared__ float s_m, s_dinv;
    int c = cnt[i];
    if (t < c) sj[t] = nbr[i * CAP + t];
    __syncthreads();
    float fi = f[h * n + i];
    if (t < c) {
        float s = fi + g[h * n + sj[t]];
        sw[t] = (s >= 0.0f) ? s : LRELU_ALPHA * s;
    }
    __syncthreads();
    if (t == 0) {
        float m = -1e30f;
        for (int k = 0; k < c; k++) m = fmaxf(m, sw[k]);
        s_m = m;
    }
    __syncthreads();
    if (t < c) sw[t] = expf(sw[t] - s_m);
    __syncthreads();
    if (t == 0) {
        float d = 0.0f;
        for (int k = 0; k < c; k++) d += sw[k];
        s_dinv = 1.0f / d;
    }
    __syncthreads();
    const float* base = Wh + (size_t)h * n * Dd;
    float acc = 0.0f;
    for (int k = 0; k < c; k++)
        acc += sw[k] * base[(size_t)sj[k] * Dd + t];
    acc *= s_dinv;
    float o = (acc > 0.0f) ? acc : expm1f(acc);
    hcat[(size_t)i * (NHd * Dd) + h * Dd + t] = o;
}

// ------------------------- gated fusion elementwise ------------------------
__global__ void fuse_kernel(const float* __restrict__ a, const float* __restrict__ b,
                            float* __restrict__ out, int total) {
    int idx = blockIdx.x * blockDim.x + threadIdx.x;
    if (idx < total) {
        float ca = a[idx], cb = b[idx];
        float z = 1.0f / (1.0f + expf(-(ca + cb)));
        out[idx] = z * ca + (1.0f - z) * cb;
    }
}

// ------------------------- sparse adj @ X (GCN), optional ReLU -------------
__global__ void spmm_kernel(const int* __restrict__ nbr, const float* __restrict__ val,
                            const int* __restrict__ cnt, const float* __restrict__ X,
                            float* __restrict__ Y, int ncols, int do_relu) {
    int i = blockIdx.x;
    int t = threadIdx.x;
    int c = cnt[i];
    float acc = 0.0f;
    for (int k = 0; k < c; k++) {
        int j = nbr[i * CAP + k];
        acc += val[i * CAP + k] * X[(size_t)j * ncols + t];
    }
    if (do_relu) acc = fmaxf(acc, 0.0f);
    Y[(size_t)i * ncols + t] = acc;
}

// ------------------------- host-side launch helpers ------------------------
static inline void run_mma_nn(const float* A, const float* B, const float* bias,
                              float* C, int M, int N, int K, int batch = 1,
                              size_t sA = 0, size_t sB = 0, size_t sC = 0) {
    dim3 grid(N / BNt, M / BMt, batch);
    mma_gemm_kernel<false, false><<<grid, 256>>>(A, B, bias, C, M, N, K, sA, sB, sC);
}
static inline void run_mma_tn(const float* A, const float* B, const float* bias,
                              float* C, int M, int N, int K) {
    dim3 grid(N / BNt, M / BMt, 1);
    mma_gemm_kernel<true, false><<<grid, 256>>>(A, B, bias, C, M, N, K, 0, 0, 0);
}
static inline void run_mma_nt(const float* A, const float* B, const float* bias,
                              float* C, int M, int N, int K) {
    dim3 grid(N / BNt, M / BMt, 1);
    mma_gemm_kernel<false, true><<<grid, 256>>>(A, B, bias, C, M, N, K, 0, 0, 0);
}

extern "C" void kernel_launch(void* const* d_in, const int* in_sizes, int n_in,
                              void* d_out, int out_size) {
    const float* x        = (const float*)d_in[0];
    const float* adj      = (const float*)d_in[1];
    const float* t_x      = (const float*)d_in[2];
    const float* t_adj    = (const float*)d_in[3];
    const float* tfidf    = (const float*)d_in[4];
    const float* gat_W    = (const float*)d_in[5];
    const float* gat_asrc = (const float*)d_in[6];
    const float* gat_adst = (const float*)d_in[7];
    const float* gat_fcW  = (const float*)d_in[8];
    const float* gat_fcb  = (const float*)d_in[9];
    const float* t_W      = (const float*)d_in[10];
    const float* t_asrc   = (const float*)d_in[11];
    const float* t_adst   = (const float*)d_in[12];
    const float* t_fcW    = (const float*)d_in[13];
    const float* t_fcb    = (const float*)d_in[14];
    const float* fus_W    = (const float*)d_in[15];
    const float* fus_b    = (const float*)d_in[16];
    const float* gc1_W    = (const float*)d_in[17];
    const float* gc2_W    = (const float*)d_in[18];
    const float* gc3_W    = (const float*)d_in[19];

    float* out    = (float*)d_out;
    float* mu     = out + (size_t)Nn * Nn;
    float* logvar = mu + (size_t)Nn * H2d;

    float *Wh_c, *Wh_t, *f_c, *g_c, *f_t, *g_t, *val_c, *val_t;
    float *hcat_c, *hcat_t, *concept, *gtext, *ctext, *fused, *fusion, *tmp1, *h1, *tmp2;
    int *nbr_c, *cnt_c, *nbr_t, *cnt_t;
    cudaGetSymbolAddress((void**)&Wh_c,   g_Wh_c);
    cudaGetSymbolAddress((void**)&Wh_t,   g_Wh_t);
    cudaGetSymbolAddress((void**)&f_c,    g_f_c);
    cudaGetSymbolAddress((void**)&g_c,    g_g_c);
    cudaGetSymbolAddress((void**)&f_t,    g_f_t);
    cudaGetSymbolAddress((void**)&g_t,    g_g_t);
    cudaGetSymbolAddress((void**)&nbr_c,  g_nbr_c);
    cudaGetSymbolAddress((void**)&val_c,  g_val_c);
    cudaGetSymbolAddress((void**)&cnt_c,  g_cnt_c);
    cudaGetSymbolAddress((void**)&nbr_t,  g_nbr_t);
    cudaGetSymbolAddress((void**)&val_t,  g_val_t);
    cudaGetSymbolAddress((void**)&cnt_t,  g_cnt_t);
    cudaGetSymbolAddress((void**)&hcat_c, g_hcat_c);
    cudaGetSymbolAddress((void**)&hcat_t, g_hcat_t);
    cudaGetSymbolAddress((void**)&concept,g_concept);
    cudaGetSymbolAddress((void**)&gtext,  g_gtext);
    cudaGetSymbolAddress((void**)&ctext,  g_ctext);
    cudaGetSymbolAddress((void**)&fused,  g_fused);
    cudaGetSymbolAddress((void**)&fusion, g_fusion);
    cudaGetSymbolAddress((void**)&tmp1,   g_tmp1);
    cudaGetSymbolAddress((void**)&h1,     g_h1);
    cudaGetSymbolAddress((void**)&tmp2,   g_tmp2);

    // 1) adjacency -> CSR
    build_csr_kernel<<<Nn, 256>>>(adj, Nn, nbr_c, val_c, cnt_c);
    build_csr_kernel<<<Tt, 256>>>(t_adj, Tt, nbr_t, val_t, cnt_t);

    // 2) per-head Wh = x @ W[h]  (batched over heads)
    run_mma_nn(x,   gat_W, nullptr, Wh_c, Nn, Dd, Dd, NHd,
               0, (size_t)Dd * Dd, (size_t)Nn * Dd);
    run_mma_nn(t_x, t_W,   nullptr, Wh_t, Tt, Dd, Dd, NHd,
               0, (size_t)Dd * Dd, (size_t)Tt * Dd);

    // 3) attention projections f,g
    {
        int warps = NHd * Nn;
        fg_kernel<<<(warps * 32 + 255) / 256, 256>>>(Wh_c, gat_asrc, gat_adst, f_c, g_c, Nn);
        warps = NHd * Tt;
        fg_kernel<<<(warps * 32 + 255) / 256, 256>>>(Wh_t, t_asrc, t_adst, f_t, g_t, Tt);
    }

    // 4) sparse masked softmax attention + aggregation + ELU
    gat_attn_kernel<<<dim3(Nn, NHd), 256>>>(Wh_c, f_c, g_c, nbr_c, cnt_c, hcat_c, Nn);
    gat_attn_kernel<<<dim3(Tt, NHd), 256>>>(Wh_t, f_t, g_t, nbr_t, cnt_t, hcat_t, Tt);

    // 5) output fc per graph
    run_mma_nn(hcat_c, gat_fcW, gat_fcb, concept, Nn, Dd, NHd * Dd);
    run_mma_nn(hcat_t, t_fcW,   t_fcb,   gtext,   Tt, Dd, NHd * Dd);

    // 6) c_text = tfidf^T @ gat_text
    run_mma_tn(tfidf, gtext, nullptr, ctext, Nn, Dd, Tt);

    // 7) gated fusion + fc
    fuse_kernel<<<(Nn * Dd + 255) / 256, 256>>>(concept, ctext, fused, Nn * Dd);
    run_mma_nn(fused, fus_W, fus_b, fusion, Nn, Dd, Dd);

    // 8) GCN encoder
    run_mma_nn(fusion, gc1_W, nullptr, tmp1, Nn, H1d, Dd);
    spmm_kernel<<<Nn, H1d>>>(nbr_c, val_c, cnt_c, tmp1, h1, H1d, 1);

    sgemm_small_kernel<<<dim3(1, Nn / 64), 256>>>(h1, gc2_W, tmp2, Nn, H2d, H1d);
    spmm_kernel<<<Nn, H2d>>>(nbr_c, val_c, cnt_c, tmp2, mu, H2d, 0);

    sgemm_small_kernel<<<dim3(1, Nn / 64), 256>>>(h1, gc3_W, tmp2, Nn, H2d, H1d);
    spmm_kernel<<<Nn, H2d>>>(nbr_c, val_c, cnt_c, tmp2, logvar, H2d, 0);

    // 9) recon = mu @ mu^T
    run_mma_nt(mu, mu, nullptr, out, Nn, Nn, H2d);
}

// round 4
// speedup vs baseline: 1.6100x; 1.4491x over previous
#include <cuda_runtime.h>
#include <math.h>
#include <stdint.h>

#define Nn   4096
#define Tt   2048
#define Dd   256
#define H1d  128
#define H2d  32
#define NHd  4
#define CAP  96
#define LRELU_ALPHA 0.2f

// ------------------------- scratch (__device__ globals; no allocation) -----
__device__ float g_Wh_c[NHd * Nn * Dd];
__device__ float g_Wh_t[NHd * Tt * Dd];
__device__ float g_f_c[NHd * Nn], g_g_c[NHd * Nn];
__device__ float g_f_t[NHd * Tt], g_g_t[NHd * Tt];
__device__ int   g_nbr_c[Nn * CAP];
__device__ float g_val_c[Nn * CAP];
__device__ int   g_cnt_c[Nn];
__device__ int   g_nbr_t[Tt * CAP];
__device__ float g_val_t[Tt * CAP];
__device__ int   g_cnt_t[Tt];
__device__ float g_hcat_c[Nn * NHd * Dd];
__device__ float g_hcat_t[Tt * NHd * Dd];
__device__ float g_concept[Nn * Dd];
__device__ float g_gtext[Tt * Dd];
__device__ float g_ctext[Nn * Dd];
__device__ float g_fused[Nn * Dd];
__device__ float g_fusion[Nn * Dd];
__device__ float g_tmp1[Nn * H1d];
__device__ float g_h1[Nn * H1d];
__device__ float g_tmp2a[Nn * H2d];
__device__ float g_tmp2b[Nn * H2d];

// ------------------------- CSR build: two-pass warp-strip ------------------
__global__ void build_csr_kernel(const float* __restrict__ adj, int n,
                                 int* __restrict__ nbr, float* __restrict__ val,
                                 int* __restrict__ cnt) {
    int i = blockIdx.x;
    const float* row = adj + (size_t)i * n;
    int t = threadIdx.x, lane = t & 31, w = t >> 5;
    int strip = n >> 3;            // 8 warps
    int s0 = w * strip;
    __shared__ int s_cnt[8];
    // pass 1: count per warp strip
    int my = 0;
    for (int b = s0; b < s0 + strip; b += 32) {
        bool p = row[b + lane] > 0.0f;
        unsigned m = __ballot_sync(0xffffffffu, p);
        my += __popc(m);
    }
    if (lane == 0) s_cnt[w] = my;
    __syncthreads();
    int off = 0;
    #pragma unroll
    for (int ww = 0; ww < 8; ww++) if (ww < w) off += s_cnt[ww];
    int tot = 0;
    #pragma unroll
    for (int ww = 0; ww < 8; ww++) tot += s_cnt[ww];
    // pass 2: write (row now hot in cache)
    for (int b = s0; b < s0 + strip; b += 32) {
        float v = row[b + lane];
        bool p = v > 0.0f;
        unsigned m = __ballot_sync(0xffffffffu, p);
        int pos = off + __popc(m & ((1u << lane) - 1u));
        if (p && pos < CAP) { nbr[i * CAP + pos] = b + lane; val[i * CAP + pos] = v; }
        off += __popc(m);
    }
    if (t == 0) cnt[i] = min(tot, CAP);
}

// ------------------------- tf32 helpers ------------------------------------
__device__ __forceinline__ void tf32_split_u(float v, uint32_t& h, uint32_t& l) {
    asm("cvt.rna.tf32.f32 %0, %1;" : "=r"(h) : "f"(v));
    float r = v - __uint_as_float(h);
    asm("cvt.rna.tf32.f32 %0, %1;" : "=r"(l) : "f"(r));
}

#define MMA_TF32(c, a, b)                                                         \
    asm volatile(                                                                  \
        "mma.sync.aligned.m16n8k8.row.col.f32.tf32.tf32.f32 "                      \
        "{%0,%1,%2,%3},{%4,%5,%6,%7},{%8,%9},{%0,%1,%2,%3};"                       \
        : "+f"((c)[0]), "+f"((c)[1]), "+f"((c)[2]), "+f"((c)[3])                   \
        : "r"((a)[0]), "r"((a)[1]), "r"((a)[2]), "r"((a)[3]),                      \
          "r"((b)[0]), "r"((b)[1]))

__device__ __forceinline__ void cp16(void* sp, const void* gp) {
    uint32_t s = (uint32_t)__cvta_generic_to_shared(sp);
    asm volatile("cp.async.cg.shared.global [%0], [%1], 16;" :: "r"(s), "l"(gp));
}

// ------------------------- tensor-core 3xTF32 GEMM (cp.async 2-stage) ------
// C = op(A) @ op(B) [+ bias], fp32 in/out.
// op(A): TA ? A=[K,M] : A=[M,K]; op(B): TB ? B=[N,K] : B=[K,N] (row-major).
// M%128==0, N%64==0, K%16==0. Batched over blockIdx.z.
#define BMt 128
#define BNt 64
#define BKt 16

template <bool TA, bool TB>
__global__ void __launch_bounds__(256) mma_gemm_kernel(
    const float* __restrict__ A, const float* __restrict__ B,
    const float* __restrict__ bias, float* __restrict__ C,
    int M, int N, int K, size_t sA, size_t sB, size_t sC) {
    constexpr int AR = TA ? BKt : BMt;
    constexpr int AC = TA ? (BMt + 4) : (BKt + 4);
    constexpr int BR = TB ? BNt : BKt;
    constexpr int BC = TB ? (BKt + 4) : (BNt + 4);
    __shared__ float As[2][AR][AC];
    __shared__ float Bs[2][BR][BC];

    const float* Ab = A + (size_t)blockIdx.z * sA;
    const float* Bb = B + (size_t)blockIdx.z * sB;
    float* Cb = C + (size_t)blockIdx.z * sC;
    int bm = blockIdx.y * BMt, bn = blockIdx.x * BNt;
    int t = threadIdx.x, lane = t & 31, w = t >> 5;
    int wm = (w & 3) * 32, wn = (w >> 2) * 32;
    int gid = lane >> 2, tig = lane & 3;

    float acc[2][4][4] = {};

    auto load_tile = [&](int s, int k0) {
        if (!TA) {
            #pragma unroll
            for (int j = 0; j < 2; j++) {
                int idx = t + j * 256;
                int row = idx >> 2;           // 0..127 (m)
                int col = (idx & 3) * 4;      // 0..12  (k)
                cp16(&As[s][row][col], Ab + (size_t)(bm + row) * K + k0 + col);
            }
        } else {
            #pragma unroll
            for (int j = 0; j < 2; j++) {
                int idx = t + j * 256;
                int row = idx >> 5;           // 0..15  (k)
                int col = (idx & 31) * 4;     // 0..124 (m)
                cp16(&As[s][row][col], Ab + (size_t)(k0 + row) * M + bm + col);
            }
        }
        if (!TB) {
            int row = t >> 4;                 // 0..15 (k)
            int col = (t & 15) * 4;           // 0..60 (n)
            cp16(&Bs[s][row][col], Bb + (size_t)(k0 + row) * N + bn + col);
        } else {
            int row = t >> 2;                 // 0..63 (n)
            int col = (t & 3) * 4;            // 0..12 (k)
            cp16(&Bs[s][row][col], Bb + (size_t)(bn + row) * K + k0 + col);
        }
    };

    auto Ae = [&](int s, int k, int m) -> float {
        return TA ? As[s][k][m] : As[s][m][k];
    };
    auto Be = [&](int s, int k, int nn) -> float {
        return TB ? Bs[s][nn][k] : Bs[s][k][nn];
    };

    int nk = K / BKt;
    load_tile(0, 0);
    asm volatile("cp.async.commit_group;");

    for (int kt = 0; kt < nk; kt++) {
        int s = kt & 1;
        if (kt + 1 < nk) {
            load_tile(s ^ 1, (kt + 1) * BKt);
            asm volatile("cp.async.commit_group;");
            asm volatile("cp.async.wait_group 1;");
        } else {
            asm volatile("cp.async.wait_group 0;");
        }
        __syncthreads();

        #pragma unroll
        for (int kk = 0; kk < BKt; kk += 8) {
            uint32_t ah[2][4], al[2][4], bh[4][2], bl[4][2];
            #pragma unroll
            for (int mt = 0; mt < 2; mt++) {
                int m0 = wm + mt * 16 + gid;
                tf32_split_u(Ae(s, kk + tig,     m0),     ah[mt][0], al[mt][0]);
                tf32_split_u(Ae(s, kk + tig,     m0 + 8), ah[mt][1], al[mt][1]);
                tf32_split_u(Ae(s, kk + tig + 4, m0),     ah[mt][2], al[mt][2]);
                tf32_split_u(Ae(s, kk + tig + 4, m0 + 8), ah[mt][3], al[mt][3]);
            }
            #pragma unroll
            for (int nt = 0; nt < 4; nt++) {
                int n0 = wn + nt * 8 + gid;
                tf32_split_u(Be(s, kk + tig,     n0), bh[nt][0], bl[nt][0]);
                tf32_split_u(Be(s, kk + tig + 4, n0), bh[nt][1], bl[nt][1]);
            }
            #pragma unroll
            for (int mt = 0; mt < 2; mt++)
                #pragma unroll
                for (int nt = 0; nt < 4; nt++) {
                    MMA_TF32(acc[mt][nt], al[mt], bh[nt]);
                    MMA_TF32(acc[mt][nt], ah[mt], bl[nt]);
                    MMA_TF32(acc[mt][nt], ah[mt], bh[nt]);
                }
        }
        __syncthreads();
    }

    #pragma unroll
    for (int mt = 0; mt < 2; mt++) {
        int row0 = bm + wm + mt * 16 + gid;
        #pragma unroll
        for (int nt = 0; nt < 4; nt++) {
            int col = bn + wn + nt * 8 + tig * 2;
            float bx = bias ? bias[col] : 0.0f;
            float by = bias ? bias[col + 1] : 0.0f;
            *reinterpret_cast<float2*>(&Cb[(size_t)row0 * N + col]) =
                make_float2(acc[mt][nt][0] + bx, acc[mt][nt][1] + by);
            *reinterpret_cast<float2*>(&Cb[(size_t)(row0 + 8) * N + col]) =
                make_float2(acc[mt][nt][2] + bx, acc[mt][nt][3] + by);
        }
    }
}

// ------------------------- gc2 & gc3 fused SIMT GEMM (N=32 each) -----------
__global__ void gc23_kernel(const float* __restrict__ A, const float* __restrict__ B2,
                            const float* __restrict__ B3, float* __restrict__ C2,
                            float* __restrict__ C3) {
    __shared__ __align__(16) float As[16][64];
    __shared__ __align__(16) float Bs[16][64];
    int bm = blockIdx.x * 64;
    int t = threadIdx.x, tx = t & 15, ty = t >> 4;
    float acc[4][4] = {};
    for (int k0 = 0; k0 < H1d; k0 += 16) {
        #pragma unroll
        for (int j = 0; j < 4; j++) {
            int li = t + j * 256;
            int r = li >> 4, c = li & 15;
            As[c][r] = A[(size_t)(bm + r) * H1d + k0 + c];
            int rb = li >> 6, cb = li & 63;
            Bs[rb][cb] = (cb < 32) ? B2[(k0 + rb) * H2d + cb]
                                   : B3[(k0 + rb) * H2d + cb - 32];
        }
        __syncthreads();
        #pragma unroll
        for (int k = 0; k < 16; k++) {
            float4 a4 = *reinterpret_cast<const float4*>(&As[k][ty << 2]);
            float4 b4 = *reinterpret_cast<const float4*>(&Bs[k][tx << 2]);
            float a[4] = {a4.x, a4.y, a4.z, a4.w};
            float b[4] = {b4.x, b4.y, b4.z, b4.w};
            #pragma unroll
            for (int u = 0; u < 4; u++)
                #pragma unroll
                for (int v = 0; v < 4; v++)
                    acc[u][v] += a[u] * b[v];
        }
        __syncthreads();
    }
    #pragma unroll
    for (int u = 0; u < 4; u++) {
        int row = bm + (ty << 2) + u;
        #pragma unroll
        for (int v = 0; v < 4; v++) {
            int col = (tx << 2) + v;
            if (col < 32) C2[(size_t)row * H2d + col] = acc[u][v];
            else          C3[(size_t)row * H2d + col - 32] = acc[u][v];
        }
    }
}

// ------------------------- f/g projections ---------------------------------
__global__ void fg_kernel(const float* __restrict__ Wh, const float* __restrict__ asrc,
                          const float* __restrict__ adst, float* __restrict__ f,
                          float* __restrict__ g, int n) {
    int gw = (blockIdx.x * blockDim.x + threadIdx.x) >> 5;
    int lane = threadIdx.x & 31;
    if (gw >= NHd * n) return;
    int h = gw / n, i = gw - h * n;
    const float* w  = Wh + ((size_t)h * n + i) * Dd;
    const float* as = asrc + h * Dd;
    const float* ad = adst + h * Dd;
    float accf = 0.0f, accg = 0.0f;
    #pragma unroll
    for (int c = 0; c < Dd / 32; c++) {
        float v = w[lane + 32 * c];
        accf += v * as[lane + 32 * c];
        accg += v * ad[lane + 32 * c];
    }
    #pragma unroll
    for (int o = 16; o; o >>= 1) {
        accf += __shfl_down_sync(0xffffffffu, accf, o);
        accg += __shfl_down_sync(0xffffffffu, accg, o);
    }
    if (lane == 0) { f[gw] = accf; g[gw] = accg; }
}

// ------------------------- sparse GAT attention + aggregation + ELU --------
__global__ void gat_attn_kernel(const float* __restrict__ Wh, const float* __restrict__ f,
                                const float* __restrict__ g, const int* __restrict__ nbr,
                                const int* __restrict__ cnt, float* __restrict__ hcat, int n) {
    int i = blockIdx.x, h = blockIdx.y;
    int t = threadIdx.x, lane = t & 31, w = t >> 5;
    __shared__ int   sj[CAP];
    __shared__ float sw[CAP];
    __shared__ float s_red[8];
    __shared__ float s_m, s_dinv;
    int c = cnt[i];
    if (t < c) sj[t] = nbr[i * CAP + t];
    __syncthreads();
    float fi = f[h * n + i];
    float sc = -1e30f;
    if (t < c) {
        float s = fi + g[h * n + sj[t]];
        sc = (s >= 0.0f) ? s : LRELU_ALPHA * s;
    }
    // block max
    float v = sc;
    #pragma unroll
    for (int o = 16; o; o >>= 1) v = fmaxf(v, __shfl_xor_sync(0xffffffffu, v, o));
    if (lane == 0) s_red[w] = v;
    __syncthreads();
    if (t == 0) {
        float m = s_red[0];
        #pragma unroll
        for (int j = 1; j < 8; j++) m = fmaxf(m, s_red[j]);
        s_m = m;
    }
    __syncthreads();
    float ev = 0.0f;
    if (t < c) { ev = expf(sc - s_m); sw[t] = ev; }
    // block sum
    float sv = ev;
    #pragma unroll
    for (int o = 16; o; o >>= 1) sv += __shfl_xor_sync(0xffffffffu, sv, o);
    if (lane == 0) s_red[w] = sv;
    __syncthreads();
    if (t == 0) {
        float d = 0.0f;
        #pragma unroll
        for (int j = 0; j < 8; j++) d += s_red[j];
        s_dinv = 1.0f / d;
    }
    __syncthreads();
    const float* base = Wh + (size_t)h * n * Dd;
    float a0 = 0.0f, a1 = 0.0f, a2 = 0.0f, a3 = 0.0f;
    int k = 0;
    for (; k + 4 <= c; k += 4) {
        a0 += sw[k]     * __ldg(base + (size_t)sj[k]     * Dd + t);
        a1 += sw[k + 1] * __ldg(base + (size_t)sj[k + 1] * Dd + t);
        a2 += sw[k + 2] * __ldg(base + (size_t)sj[k + 2] * Dd + t);
        a3 += sw[k + 3] * __ldg(base + (size_t)sj[k + 3] * Dd + t);
    }
    for (; k < c; k++)
        a0 += sw[k] * __ldg(base + (size_t)sj[k] * Dd + t);
    float acc = ((a0 + a1) + (a2 + a3)) * s_dinv;
    float o = (acc > 0.0f) ? acc : expm1f(acc);
    hcat[(size_t)i * (NHd * Dd) + h * Dd + t] = o;
}

// ------------------------- gated fusion elementwise ------------------------
__global__ void fuse_kernel(const float* __restrict__ a, const float* __restrict__ b,
                            float* __restrict__ out, int total) {
    int idx = blockIdx.x * blockDim.x + threadIdx.x;
    if (idx < total) {
        float ca = a[idx], cb = b[idx];
        float z = 1.0f / (1.0f + expf(-(ca + cb)));
        out[idx] = z * ca + (1.0f - z) * cb;
    }
}

// ------------------------- sparse adj @ X, optional ReLU (unroll 4) --------
__global__ void spmm_kernel(const int* __restrict__ nbr, const float* __restrict__ val,
                            const int* __restrict__ cnt, const float* __restrict__ X,
                            float* __restrict__ Y, int ncols, int do_relu) {
    int i = blockIdx.x;
    int t = threadIdx.x;
    int c = cnt[i];
    const int* jb = nbr + i * CAP;
    const float* vb = val + i * CAP;
    float a0 = 0.0f, a1 = 0.0f, a2 = 0.0f, a3 = 0.0f;
    int k = 0;
    for (; k + 4 <= c; k += 4) {
        a0 += vb[k]     * __ldg(X + (size_t)jb[k]     * ncols + t);
        a1 += vb[k + 1] * __ldg(X + (size_t)jb[k + 1] * ncols + t);
        a2 += vb[k + 2] * __ldg(X + (size_t)jb[k + 2] * ncols + t);
        a3 += vb[k + 3] * __ldg(X + (size_t)jb[k + 3] * ncols + t);
    }
    for (; k < c; k++)
        a0 += vb[k] * __ldg(X + (size_t)jb[k] * ncols + t);
    float acc = (a0 + a1) + (a2 + a3);
    if (do_relu) acc = fmaxf(acc, 0.0f);
    Y[(size_t)i * ncols + t] = acc;
}

// ------------------------- fused mu/logvar spmm (ncols=32 each) ------------
__global__ void spmm2_kernel(const int* __restrict__ nbr, const float* __restrict__ val,
                             const int* __restrict__ cnt, const float* __restrict__ X2,
                             const float* __restrict__ X3, float* __restrict__ mu,
                             float* __restrict__ logvar) {
    int i = blockIdx.x;
    int t = threadIdx.x;            // 64 threads
    int sel = t >> 5, col = t & 31;
    const float* X = sel ? X3 : X2;
    float* Y = sel ? logvar : mu;
    int c = cnt[i];
    const int* jb = nbr + i * CAP;
    const float* vb = val + i * CAP;
    float a0 = 0.0f, a1 = 0.0f, a2 = 0.0f, a3 = 0.0f;
    int k = 0;
    for (; k + 4 <= c; k += 4) {
        a0 += vb[k]     * __ldg(X + (size_t)jb[k]     * H2d + col);
        a1 += vb[k + 1] * __ldg(X + (size_t)jb[k + 1] * H2d + col);
        a2 += vb[k + 2] * __ldg(X + (size_t)jb[k + 2] * H2d + col);
        a3 += vb[k + 3] * __ldg(X + (size_t)jb[k + 3] * H2d + col);
    }
    for (; k < c; k++)
        a0 += vb[k] * __ldg(X + (size_t)jb[k] * H2d + col);
    Y[(size_t)i * H2d + col] = (a0 + a1) + (a2 + a3);
}

// ------------------------- host-side launch helpers ------------------------
static inline void run_mma_nn(const float* A, const float* B, const float* bias,
                              float* C, int M, int N, int K, int batch = 1,
                              size_t sA = 0, size_t sB = 0, size_t sC = 0) {
    dim3 grid(N / BNt, M / BMt, batch);
    mma_gemm_kernel<false, false><<<grid, 256>>>(A, B, bias, C, M, N, K, sA, sB, sC);
}
static inline void run_mma_tn(const float* A, const float* B, const float* bias,
                              float* C, int M, int N, int K) {
    dim3 grid(N / BNt, M / BMt, 1);
    mma_gemm_kernel<true, false><<<grid, 256>>>(A, B, bias, C, M, N, K, 0, 0, 0);
}
static inline void run_mma_nt(const float* A, const float* B, const float* bias,
                              float* C, int M, int N, int K) {
    dim3 grid(N / BNt, M / BMt, 1);
    mma_gemm_kernel<false, true><<<grid, 256>>>(A, B, bias, C, M, N, K, 0, 0, 0);
}

extern "C" void kernel_launch(void* const* d_in, const int* in_sizes, int n_in,
                              void* d_out, int out_size) {
    const float* x        = (const float*)d_in[0];
    const float* adj      = (const float*)d_in[1];
    const float* t_x      = (const float*)d_in[2];
    const float* t_adj    = (const float*)d_in[3];
    const float* tfidf    = (const float*)d_in[4];
    const float* gat_W    = (const float*)d_in[5];
    const float* gat_asrc = (const float*)d_in[6];
    const float* gat_adst = (const float*)d_in[7];
    const float* gat_fcW  = (const float*)d_in[8];
    const float* gat_fcb  = (const float*)d_in[9];
    const float* t_W      = (const float*)d_in[10];
    const float* t_asrc   = (const float*)d_in[11];
    const float* t_adst   = (const float*)d_in[12];
    const float* t_fcW    = (const float*)d_in[13];
    const float* t_fcb    = (const float*)d_in[14];
    const float* fus_W    = (const float*)d_in[15];
    const float* fus_b    = (const float*)d_in[16];
    const float* gc1_W    = (const float*)d_in[17];
    const float* gc2_W    = (const float*)d_in[18];
    const float* gc3_W    = (const float*)d_in[19];

    float* out    = (float*)d_out;
    float* mu     = out + (size_t)Nn * Nn;
    float* logvar = mu + (size_t)Nn * H2d;

    float *Wh_c, *Wh_t, *f_c, *g_c, *f_t, *g_t, *val_c, *val_t;
    float *hcat_c, *hcat_t, *concept, *gtext, *ctext, *fused, *fusion;
    float *tmp1, *h1, *tmp2a, *tmp2b;
    int *nbr_c, *cnt_c, *nbr_t, *cnt_t;
    cudaGetSymbolAddress((void**)&Wh_c,   g_Wh_c);
    cudaGetSymbolAddress((void**)&Wh_t,   g_Wh_t);
    cudaGetSymbolAddress((void**)&f_c,    g_f_c);
    cudaGetSymbolAddress((void**)&g_c,    g_g_c);
    cudaGetSymbolAddress((void**)&f_t,    g_f_t);
    cudaGetSymbolAddress((void**)&g_t,    g_g_t);
    cudaGetSymbolAddress((void**)&nbr_c,  g_nbr_c);
    cudaGetSymbolAddress((void**)&val_c,  g_val_c);
    cudaGetSymbolAddress((void**)&cnt_c,  g_cnt_c);
    cudaGetSymbolAddress((void**)&nbr_t,  g_nbr_t);
    cudaGetSymbolAddress((void**)&val_t,  g_val_t);
    cudaGetSymbolAddress((void**)&cnt_t,  g_cnt_t);
    cudaGetSymbolAddress((void**)&hcat_c, g_hcat_c);
    cudaGetSymbolAddress((void**)&hcat_t, g_hcat_t);
    cudaGetSymbolAddress((void**)&concept,g_concept);
    cudaGetSymbolAddress((void**)&gtext,  g_gtext);
    cudaGetSymbolAddress((void**)&ctext,  g_ctext);
    cudaGetSymbolAddress((void**)&fused,  g_fused);
    cudaGetSymbolAddress((void**)&fusion, g_fusion);
    cudaGetSymbolAddress((void**)&tmp1,   g_tmp1);
    cudaGetSymbolAddress((void**)&h1,     g_h1);
    cudaGetSymbolAddress((void**)&tmp2a,  g_tmp2a);
    cudaGetSymbolAddress((void**)&tmp2b,  g_tmp2b);

    // 1) adjacency -> CSR
    build_csr_kernel<<<Nn, 256>>>(adj, Nn, nbr_c, val_c, cnt_c);
    build_csr_kernel<<<Tt, 256>>>(t_adj, Tt, nbr_t, val_t, cnt_t);

    // 2) per-head Wh = x @ W[h]  (batched over heads)
    run_mma_nn(x,   gat_W, nullptr, Wh_c, Nn, Dd, Dd, NHd,
               0, (size_t)Dd * Dd, (size_t)Nn * Dd);
    run_mma_nn(t_x, t_W,   nullptr, Wh_t, Tt, Dd, Dd, NHd,
               0, (size_t)Dd * Dd, (size_t)Tt * Dd);

    // 3) attention projections f,g
    {
        int warps = NHd * Nn;
        fg_kernel<<<(warps * 32 + 255) / 256, 256>>>(Wh_c, gat_asrc, gat_adst, f_c, g_c, Nn);
        warps = NHd * Tt;
        fg_kernel<<<(warps * 32 + 255) / 256, 256>>>(Wh_t, t_asrc, t_adst, f_t, g_t, Tt);
    }

    // 4) sparse masked softmax attention + aggregation + ELU
    gat_attn_kernel<<<dim3(Nn, NHd), 256>>>(Wh_c, f_c, g_c, nbr_c, cnt_c, hcat_c, Nn);
    gat_attn_kernel<<<dim3(Tt, NHd), 256>>>(Wh_t, f_t, g_t, nbr_t, cnt_t, hcat_t, Tt);

    // 5) output fc per graph
    run_mma_nn(hcat_c, gat_fcW, gat_fcb, concept, Nn, Dd, NHd * Dd);
    run_mma_nn(hcat_t, t_fcW,   t_fcb,   gtext,   Tt, Dd, NHd * Dd);

    // 6) c_text = tfidf^T @ gat_text
    run_mma_tn(tfidf, gtext, nullptr, ctext, Nn, Dd, Tt);

    // 7) gated fusion + fc
    fuse_kernel<<<(Nn * Dd + 255) / 256, 256>>>(concept, ctext, fused, Nn * Dd);
    run_mma_nn(fused, fus_W, fus_b, fusion, Nn, Dd, Dd);

    // 8) GCN encoder
    run_mma_nn(fusion, gc1_W, nullptr, tmp1, Nn, H1d, Dd);
    spmm_kernel<<<Nn, H1d>>>(nbr_c, val_c, cnt_c, tmp1, h1, H1d, 1);

    gc23_kernel<<<Nn / 64, 256>>>(h1, gc2_W, gc3_W, tmp2a, tmp2b);
    spmm2_kernel<<<Nn, 64>>>(nbr_c, val_c, cnt_c, tmp2a, tmp2b, mu, logvar);

    // 9) recon = mu @ mu^T
    run_mma_nt(mu, mu, nullptr, out, Nn, Nn, H2d);
}

// round 5
// speedup vs baseline: 1.6262x; 1.0100x over previous
#include <cuda_runtime.h>
#include <math.h>
#include <stdint.h>

#define Nn   4096
#define Tt   2048
#define Dd   256
#define H1d  128
#define H2d  32
#define NHd  4
#define CAP  96
#define LRELU_ALPHA 0.2f

// ------------------------- scratch (__device__ globals) --------------------
__device__ float g_Wh_c[NHd * Nn * Dd];
__device__ float g_Wh_t[NHd * Tt * Dd];
__device__ float g_f_c[NHd * Nn], g_g_c[NHd * Nn];
__device__ float g_f_t[NHd * Tt], g_g_t[NHd * Tt];
__device__ int   g_nbr_c[Nn * CAP];
__device__ float g_val_c[Nn * CAP];
__device__ int   g_cnt_c[Nn];
__device__ int   g_nbr_t[Tt * CAP];
__device__ float g_val_t[Tt * CAP];
__device__ int   g_cnt_t[Tt];
__device__ float g_concept[Nn * Dd];
__device__ float g_ctext[Nn * Dd];
__device__ float g_tmp1[Nn * H1d];
__device__ float g_h1[Nn * H1d];
__device__ float g_tmp2a[Nn * H2d];
__device__ float g_tmp2b[Nn * H2d];
// hi/lo planes
__device__ float g_x_h[Nn * Dd],        g_x_l[Nn * Dd];
__device__ float g_tx_h[Tt * Dd],       g_tx_l[Tt * Dd];
__device__ float g_tf_h[Tt * Nn],       g_tf_l[Tt * Nn];
__device__ float g_gatW_h[NHd * Dd * Dd], g_gatW_l[NHd * Dd * Dd];
__device__ float g_tW_h[NHd * Dd * Dd],   g_tW_l[NHd * Dd * Dd];
__device__ float g_fcWc_h[NHd * Dd * Dd], g_fcWc_l[NHd * Dd * Dd];
__device__ float g_fcWt_h[NHd * Dd * Dd], g_fcWt_l[NHd * Dd * Dd];
__device__ float g_fusW_h[Dd * Dd],     g_fusW_l[Dd * Dd];
__device__ float g_gc1W_h[Dd * H1d],    g_gc1W_l[Dd * H1d];
__device__ float g_hcatc_h[Nn * NHd * Dd], g_hcatc_l[Nn * NHd * Dd];
__device__ float g_hcatt_h[Tt * NHd * Dd], g_hcatt_l[Tt * NHd * Dd];
__device__ float g_gtext_h[Tt * Dd],    g_gtext_l[Tt * Dd];
__device__ float g_fused_h[Nn * Dd],    g_fused_l[Nn * Dd];
__device__ float g_fusion_h[Nn * Dd],   g_fusion_l[Nn * Dd];
__device__ float g_mu_h[Nn * H2d],      g_mu_l[Nn * H2d];

// ------------------------- tf32 helpers ------------------------------------
__device__ __forceinline__ void tf32_split_u(float v, uint32_t& h, uint32_t& l) {
    asm("cvt.rna.tf32.f32 %0, %1;" : "=r"(h) : "f"(v));
    float r = v - __uint_as_float(h);
    asm("cvt.rna.tf32.f32 %0, %1;" : "=r"(l) : "f"(r));
}
__device__ __forceinline__ void split_store(float v, float* hp, float* lp, size_t idx) {
    uint32_t h, l; tf32_split_u(v, h, l);
    hp[idx] = __uint_as_float(h); lp[idx] = __uint_as_float(l);
}

#define MMA_TF32(c, a, b)                                                         \
    asm volatile(                                                                  \
        "mma.sync.aligned.m16n8k8.row.col.f32.tf32.tf32.f32 "                      \
        "{%0,%1,%2,%3},{%4,%5,%6,%7},{%8,%9},{%0,%1,%2,%3};"                       \
        : "+f"((c)[0]), "+f"((c)[1]), "+f"((c)[2]), "+f"((c)[3])                   \
        : "r"((a)[0]), "r"((a)[1]), "r"((a)[2]), "r"((a)[3]),                      \
          "r"((b)[0]), "r"((b)[1]))

__device__ __forceinline__ void cp16(void* sp, const void* gp) {
    uint32_t s = (uint32_t)__cvta_generic_to_shared(sp);
    asm volatile("cp.async.cg.shared.global [%0], [%1], 16;" :: "r"(s), "l"(gp));
}

// ------------------------- split_all (harness inputs -> hi/lo) -------------
struct SplitJob { const float* src; float* hi; float* lo; int n4; };
struct SplitJobs9 { SplitJob j[9]; };
__global__ void split_all_kernel(SplitJobs9 jobs) {
    SplitJob jb = jobs.j[blockIdx.y];
    const float4* src = (const float4*)jb.src;
    float4* hi = (float4*)jb.hi;
    float4* lo = (float4*)jb.lo;
    for (int i = blockIdx.x * blockDim.x + threadIdx.x; i < jb.n4;
         i += gridDim.x * blockDim.x) {
        float4 v = src[i];
        uint32_t h, l;
        float4 vh, vl;
        tf32_split_u(v.x, h, l); vh.x = __uint_as_float(h); vl.x = __uint_as_float(l);
        tf32_split_u(v.y, h, l); vh.y = __uint_as_float(h); vl.y = __uint_as_float(l);
        tf32_split_u(v.z, h, l); vh.z = __uint_as_float(h); vl.z = __uint_as_float(l);
        tf32_split_u(v.w, h, l); vh.w = __uint_as_float(h); vl.w = __uint_as_float(l);
        hi[i] = vh; lo[i] = vl;
    }
}

// ------------------------- CSR build: two-pass warp-strip ------------------
__global__ void build_csr_kernel(const float* __restrict__ adj, int n,
                                 int* __restrict__ nbr, float* __restrict__ val,
                                 int* __restrict__ cnt) {
    int i = blockIdx.x;
    const float* row = adj + (size_t)i * n;
    int t = threadIdx.x, lane = t & 31, w = t >> 5;
    int strip = n >> 3;
    int s0 = w * strip;
    __shared__ int s_cnt[8];
    int my = 0;
    for (int b = s0; b < s0 + strip; b += 32) {
        bool p = row[b + lane] > 0.0f;
        unsigned m = __ballot_sync(0xffffffffu, p);
        my += __popc(m);
    }
    if (lane == 0) s_cnt[w] = my;
    __syncthreads();
    int off = 0;
    #pragma unroll
    for (int ww = 0; ww < 8; ww++) if (ww < w) off += s_cnt[ww];
    int tot = 0;
    #pragma unroll
    for (int ww = 0; ww < 8; ww++) tot += s_cnt[ww];
    for (int b = s0; b < s0 + strip; b += 32) {
        float v = row[b + lane];
        bool p = v > 0.0f;
        unsigned m = __ballot_sync(0xffffffffu, p);
        int pos = off + __popc(m & ((1u << lane) - 1u));
        if (p && pos < CAP) { nbr[i * CAP + pos] = b + lane; val[i * CAP + pos] = v; }
        off += __popc(m);
    }
    if (t == 0) cnt[i] = min(tot, CAP);
}

// ------------------------- tensor-core GEMM on pre-split hi/lo -------------
// C = op(A) @ op(B) [+ bias]; operands given as tf32-hi/lo fp32 planes.
// op(A): TA ? A=[K,M] : A=[M,K]; op(B): TB ? B=[N,K] : B=[K,N] (row-major).
// M%128==0, N%64==0, K%16==0. Batched over blockIdx.z.
// Outputs: raw C (if non-null) and/or split planes Ch/Cl (if non-null).
#define BMt 128
#define BNt 64
#define BKt 16

template <bool TA, bool TB>
__global__ void __launch_bounds__(256) mma_gemm_kernel(
    const float* __restrict__ Ah, const float* __restrict__ Al,
    const float* __restrict__ Bh, const float* __restrict__ Bl,
    const float* __restrict__ bias, float* __restrict__ C,
    float* __restrict__ Ch, float* __restrict__ Cl,
    int M, int N, int K, size_t sA, size_t sB, size_t sC) {
    constexpr int AR = TA ? BKt : BMt;
    constexpr int AC = TA ? (BMt + 8) : (BKt + 4);
    constexpr int BR = TB ? BNt : BKt;
    constexpr int BC = TB ? (BKt + 4) : (BNt + 8);
    __shared__ float As[2][2][AR][AC];   // [stage][plane][..][..]
    __shared__ float Bs[2][2][BR][BC];

    const float* Abp[2] = { Ah + (size_t)blockIdx.z * sA, Al + (size_t)blockIdx.z * sA };
    const float* Bbp[2] = { Bh + (size_t)blockIdx.z * sB, Bl + (size_t)blockIdx.z * sB };
    int bm = blockIdx.y * BMt, bn = blockIdx.x * BNt;
    int t = threadIdx.x, lane = t & 31, w = t >> 5;
    int wm = (w & 3) * 32, wn = (w >> 2) * 32;
    int gid = lane >> 2, tig = lane & 3;

    float acc[2][4][4] = {};

    auto load_tile = [&](int s, int k0) {
        #pragma unroll
        for (int p = 0; p < 2; p++) {
            if (!TA) {
                #pragma unroll
                for (int j = 0; j < 2; j++) {
                    int idx = t + j * 256;
                    int row = idx >> 2;
                    int col = (idx & 3) * 4;
                    cp16(&As[s][p][row][col], Abp[p] + (size_t)(bm + row) * K + k0 + col);
                }
            } else {
                #pragma unroll
                for (int j = 0; j < 2; j++) {
                    int idx = t + j * 256;
                    int row = idx >> 5;
                    int col = (idx & 31) * 4;
                    cp16(&As[s][p][row][col], Abp[p] + (size_t)(k0 + row) * M + bm + col);
                }
            }
            if (!TB) {
                int row = t >> 4;
                int col = (t & 15) * 4;
                cp16(&Bs[s][p][row][col], Bbp[p] + (size_t)(k0 + row) * N + bn + col);
            } else {
                int row = t >> 2;
                int col = (t & 3) * 4;
                cp16(&Bs[s][p][row][col], Bbp[p] + (size_t)(bn + row) * K + k0 + col);
            }
        }
    };

    auto Ae = [&](int s, int p, int k, int m) -> float {
        return TA ? As[s][p][k][m] : As[s][p][m][k];
    };
    auto Be = [&](int s, int p, int k, int nn) -> float {
        return TB ? Bs[s][p][nn][k] : Bs[s][p][k][nn];
    };

    int nk = K / BKt;
    load_tile(0, 0);
    asm volatile("cp.async.commit_group;");

    for (int kt = 0; kt < nk; kt++) {
        int s = kt & 1;
        if (kt + 1 < nk) {
            load_tile(s ^ 1, (kt + 1) * BKt);
            asm volatile("cp.async.commit_group;");
            asm volatile("cp.async.wait_group 1;");
        } else {
            asm volatile("cp.async.wait_group 0;");
        }
        __syncthreads();

        #pragma unroll
        for (int kk = 0; kk < BKt; kk += 8) {
            uint32_t ah[2][4], al[2][4], bh[4][2], bl[4][2];
            #pragma unroll
            for (int mt = 0; mt < 2; mt++) {
                int m0 = wm + mt * 16 + gid;
                ah[mt][0] = __float_as_uint(Ae(s, 0, kk + tig,     m0));
                ah[mt][1] = __float_as_uint(Ae(s, 0, kk + tig,     m0 + 8));
                ah[mt][2] = __float_as_uint(Ae(s, 0, kk + tig + 4, m0));
                ah[mt][3] = __float_as_uint(Ae(s, 0, kk + tig + 4, m0 + 8));
                al[mt][0] = __float_as_uint(Ae(s, 1, kk + tig,     m0));
                al[mt][1] = __float_as_uint(Ae(s, 1, kk + tig,     m0 + 8));
                al[mt][2] = __float_as_uint(Ae(s, 1, kk + tig + 4, m0));
                al[mt][3] = __float_as_uint(Ae(s, 1, kk + tig + 4, m0 + 8));
            }
            #pragma unroll
            for (int nt = 0; nt < 4; nt++) {
                int n0 = wn + nt * 8 + gid;
                bh[nt][0] = __float_as_uint(Be(s, 0, kk + tig,     n0));
                bh[nt][1] = __float_as_uint(Be(s, 0, kk + tig + 4, n0));
                bl[nt][0] = __float_as_uint(Be(s, 1, kk + tig,     n0));
                bl[nt][1] = __float_as_uint(Be(s, 1, kk + tig + 4, n0));
            }
            #pragma unroll
            for (int mt = 0; mt < 2; mt++)
                #pragma unroll
                for (int nt = 0; nt < 4; nt++) {
                    MMA_TF32(acc[mt][nt], al[mt], bh[nt]);
                    MMA_TF32(acc[mt][nt], ah[mt], bl[nt]);
                    MMA_TF32(acc[mt][nt], ah[mt], bh[nt]);
                }
        }
        __syncthreads();
    }

    float* Cb  = C  ? C  + (size_t)blockIdx.z * sC : nullptr;
    float* Chb = Ch ? Ch + (size_t)blockIdx.z * sC : nullptr;
    float* Clb = Cl ? Cl + (size_t)blockIdx.z * sC : nullptr;
    #pragma unroll
    for (int mt = 0; mt < 2; mt++) {
        int row0 = bm + wm + mt * 16 + gid;
        #pragma unroll
        for (int nt = 0; nt < 4; nt++) {
            int col = bn + wn + nt * 8 + tig * 2;
            float bx = bias ? bias[col] : 0.0f;
            float by = bias ? bias[col + 1] : 0.0f;
            float v00 = acc[mt][nt][0] + bx, v01 = acc[mt][nt][1] + by;
            float v10 = acc[mt][nt][2] + bx, v11 = acc[mt][nt][3] + by;
            size_t i0 = (size_t)row0 * N + col;
            size_t i1 = (size_t)(row0 + 8) * N + col;
            if (Cb) {
                *reinterpret_cast<float2*>(&Cb[i0]) = make_float2(v00, v01);
                *reinterpret_cast<float2*>(&Cb[i1]) = make_float2(v10, v11);
            }
            if (Chb) {
                uint32_t h, l;
                float2 h0, l0, h1, l1;
                tf32_split_u(v00, h, l); h0.x = __uint_as_float(h); l0.x = __uint_as_float(l);
                tf32_split_u(v01, h, l); h0.y = __uint_as_float(h); l0.y = __uint_as_float(l);
                tf32_split_u(v10, h, l); h1.x = __uint_as_float(h); l1.x = __uint_as_float(l);
                tf32_split_u(v11, h, l); h1.y = __uint_as_float(h); l1.y = __uint_as_float(l);
                *reinterpret_cast<float2*>(&Chb[i0]) = h0;
                *reinterpret_cast<float2*>(&Clb[i0]) = l0;
                *reinterpret_cast<float2*>(&Chb[i1]) = h1;
                *reinterpret_cast<float2*>(&Clb[i1]) = l1;
            }
        }
    }
}

// ------------------------- gc2 & gc3 fused SIMT GEMM -----------------------
__global__ void gc23_kernel(const float* __restrict__ A, const float* __restrict__ B2,
                            const float* __restrict__ B3, float* __restrict__ C2,
                            float* __restrict__ C3) {
    __shared__ __align__(16) float As[16][64];
    __shared__ __align__(16) float Bs[16][64];
    int bm = blockIdx.x * 64;
    int t = threadIdx.x, tx = t & 15, ty = t >> 4;
    float acc[4][4] = {};
    for (int k0 = 0; k0 < H1d; k0 += 16) {
        #pragma unroll
        for (int j = 0; j < 4; j++) {
            int li = t + j * 256;
            int r = li >> 4, c = li & 15;
            As[c][r] = A[(size_t)(bm + r) * H1d + k0 + c];
            int rb = li >> 6, cb = li & 63;
            Bs[rb][cb] = (cb < 32) ? B2[(k0 + rb) * H2d + cb]
                                   : B3[(k0 + rb) * H2d + cb - 32];
        }
        __syncthreads();
        #pragma unroll
        for (int k = 0; k < 16; k++) {
            float4 a4 = *reinterpret_cast<const float4*>(&As[k][ty << 2]);
            float4 b4 = *reinterpret_cast<const float4*>(&Bs[k][tx << 2]);
            float a[4] = {a4.x, a4.y, a4.z, a4.w};
            float b[4] = {b4.x, b4.y, b4.z, b4.w};
            #pragma unroll
            for (int u = 0; u < 4; u++)
                #pragma unroll
                for (int v = 0; v < 4; v++)
                    acc[u][v] += a[u] * b[v];
        }
        __syncthreads();
    }
    #pragma unroll
    for (int u = 0; u < 4; u++) {
        int row = bm + (ty << 2) + u;
        #pragma unroll
        for (int v = 0; v < 4; v++) {
            int col = (tx << 2) + v;
            if (col < 32) C2[(size_t)row * H2d + col] = acc[u][v];
            else          C3[(size_t)row * H2d + col - 32] = acc[u][v];
        }
    }
}

// ------------------------- f/g projections ---------------------------------
__global__ void fg_kernel(const float* __restrict__ Wh, const float* __restrict__ asrc,
                          const float* __restrict__ adst, float* __restrict__ f,
                          float* __restrict__ g, int n) {
    int gw = (blockIdx.x * blockDim.x + threadIdx.x) >> 5;
    int lane = threadIdx.x & 31;
    if (gw >= NHd * n) return;
    int h = gw / n, i = gw - h * n;
    const float* w  = Wh + ((size_t)h * n + i) * Dd;
    const float* as = asrc + h * Dd;
    const float* ad = adst + h * Dd;
    float accf = 0.0f, accg = 0.0f;
    #pragma unroll
    for (int c = 0; c < Dd / 32; c++) {
        float v = w[lane + 32 * c];
        accf += v * as[lane + 32 * c];
        accg += v * ad[lane + 32 * c];
    }
    #pragma unroll
    for (int o = 16; o; o >>= 1) {
        accf += __shfl_down_sync(0xffffffffu, accf, o);
        accg += __shfl_down_sync(0xffffffffu, accg, o);
    }
    if (lane == 0) { f[gw] = accf; g[gw] = accg; }
}

// ------------------------- warp-per-(i,h) GAT attention --------------------
__global__ void __launch_bounds__(256) gat_attn_warp_kernel(
    const float* __restrict__ Wh, const float* __restrict__ f,
    const float* __restrict__ g, const int* __restrict__ nbr,
    const int* __restrict__ cnt, float* __restrict__ hcat_h,
    float* __restrict__ hcat_l, int n) {
    int w = threadIdx.x >> 5, lane = threadIdx.x & 31;
    int gw = blockIdx.x * 8 + w;
    int i = gw >> 2, h = gw & 3;
    __shared__ int   sj[8][CAP];
    __shared__ float sw[8][CAP];
    int c = cnt[i];
    const int* jb = nbr + i * CAP;
    float fi = f[h * n + i];
    float m = -1e30f;
    for (int k = lane; k < c; k += 32) {
        int j = jb[k];
        sj[w][k] = j;
        float s = fi + g[h * n + j];
        s = (s >= 0.0f) ? s : LRELU_ALPHA * s;
        sw[w][k] = s;
        m = fmaxf(m, s);
    }
    #pragma unroll
    for (int o = 16; o; o >>= 1) m = fmaxf(m, __shfl_xor_sync(0xffffffffu, m, o));
    __syncwarp();
    float sum = 0.0f;
    for (int k = lane; k < c; k += 32) {
        float e = expf(sw[w][k] - m);
        sw[w][k] = e;
        sum += e;
    }
    #pragma unroll
    for (int o = 16; o; o >>= 1) sum += __shfl_xor_sync(0xffffffffu, sum, o);
    float dinv = 1.0f / sum;
    __syncwarp();
    const float* base = Wh + (size_t)h * n * Dd;
    float acc[8] = {};
    int k = 0;
    for (; k + 2 <= c; k += 2) {
        float w0 = sw[w][k], w1 = sw[w][k + 1];
        const float* r0 = base + (size_t)sj[w][k] * Dd + lane;
        const float* r1 = base + (size_t)sj[w][k + 1] * Dd + lane;
        #pragma unroll
        for (int ch = 0; ch < 8; ch++) {
            acc[ch] += w0 * __ldg(r0 + ch * 32);
            acc[ch] += w1 * __ldg(r1 + ch * 32);
        }
    }
    if (k < c) {
        float w0 = sw[w][k];
        const float* r0 = base + (size_t)sj[w][k] * Dd + lane;
        #pragma unroll
        for (int ch = 0; ch < 8; ch++) acc[ch] += w0 * __ldg(r0 + ch * 32);
    }
    size_t obase = (size_t)i * (NHd * Dd) + h * Dd + lane;
    #pragma unroll
    for (int ch = 0; ch < 8; ch++) {
        float v = acc[ch] * dinv;
        v = (v > 0.0f) ? v : expm1f(v);
        split_store(v, hcat_h, hcat_l, obase + ch * 32);
    }
}

// ------------------------- gated fusion elementwise ------------------------
__global__ void fuse_kernel(const float* __restrict__ a, const float* __restrict__ b,
                            float* __restrict__ out_h, float* __restrict__ out_l,
                            int total) {
    int idx = blockIdx.x * blockDim.x + threadIdx.x;
    if (idx < total) {
        float ca = a[idx], cb = b[idx];
        float z = 1.0f / (1.0f + expf(-(ca + cb)));
        split_store(z * ca + (1.0f - z) * cb, out_h, out_l, idx);
    }
}

// ------------------------- sparse adj @ X, optional ReLU -------------------
__global__ void spmm_kernel(const int* __restrict__ nbr, const float* __restrict__ val,
                            const int* __restrict__ cnt, const float* __restrict__ X,
                            float* __restrict__ Y, int ncols, int do_relu) {
    int i = blockIdx.x;
    int t = threadIdx.x;
    int c = cnt[i];
    const int* jb = nbr + i * CAP;
    const float* vb = val + i * CAP;
    float a0 = 0.0f, a1 = 0.0f, a2 = 0.0f, a3 = 0.0f;
    int k = 0;
    for (; k + 4 <= c; k += 4) {
        a0 += vb[k]     * __ldg(X + (size_t)jb[k]     * ncols + t);
        a1 += vb[k + 1] * __ldg(X + (size_t)jb[k + 1] * ncols + t);
        a2 += vb[k + 2] * __ldg(X + (size_t)jb[k + 2] * ncols + t);
        a3 += vb[k + 3] * __ldg(X + (size_t)jb[k + 3] * ncols + t);
    }
    for (; k < c; k++)
        a0 += vb[k] * __ldg(X + (size_t)jb[k] * ncols + t);
    float acc = (a0 + a1) + (a2 + a3);
    if (do_relu) acc = fmaxf(acc, 0.0f);
    Y[(size_t)i * ncols + t] = acc;
}

// ------------------------- fused mu/logvar spmm ----------------------------
__global__ void spmm2_kernel(const int* __restrict__ nbr, const float* __restrict__ val,
                             const int* __restrict__ cnt, const float* __restrict__ X2,
                             const float* __restrict__ X3, float* __restrict__ mu,
                             float* __restrict__ logvar, float* __restrict__ mu_h,
                             float* __restrict__ mu_l) {
    int i = blockIdx.x;
    int t = threadIdx.x;
    int sel = t >> 5, col = t & 31;
    const float* X = sel ? X3 : X2;
    int c = cnt[i];
    const int* jb = nbr + i * CAP;
    const float* vb = val + i * CAP;
    float a0 = 0.0f, a1 = 0.0f, a2 = 0.0f, a3 = 0.0f;
    int k = 0;
    for (; k + 4 <= c; k += 4) {
        a0 += vb[k]     * __ldg(X + (size_t)jb[k]     * H2d + col);
        a1 += vb[k + 1] * __ldg(X + (size_t)jb[k + 1] * H2d + col);
        a2 += vb[k + 2] * __ldg(X + (size_t)jb[k + 2] * H2d + col);
        a3 += vb[k + 3] * __ldg(X + (size_t)jb[k + 3] * H2d + col);
    }
    for (; k < c; k++)
        a0 += vb[k] * __ldg(X + (size_t)jb[k] * H2d + col);
    float v = (a0 + a1) + (a2 + a3);
    size_t idx = (size_t)i * H2d + col;
    if (sel == 0) {
        mu[idx] = v;
        split_store(v, mu_h, mu_l, idx);
    } else {
        logvar[idx] = v;
    }
}

// ------------------------- host-side launch helpers ------------------------
struct GemmArgs {
    const float *Ah, *Al, *Bh, *Bl, *bias;
    float *C, *Ch, *Cl;
};
static inline void run_nn(GemmArgs a, int M, int N, int K, int batch = 1,
                          size_t sA = 0, size_t sB = 0, size_t sC = 0) {
    dim3 grid(N / BNt, M / BMt, batch);
    mma_gemm_kernel<false, false><<<grid, 256>>>(a.Ah, a.Al, a.Bh, a.Bl, a.bias,
                                                 a.C, a.Ch, a.Cl, M, N, K, sA, sB, sC);
}
static inline void run_tn(GemmArgs a, int M, int N, int K) {
    dim3 grid(N / BNt, M / BMt, 1);
    mma_gemm_kernel<true, false><<<grid, 256>>>(a.Ah, a.Al, a.Bh, a.Bl, a.bias,
                                                a.C, a.Ch, a.Cl, M, N, K, 0, 0, 0);
}
static inline void run_nt(GemmArgs a, int M, int N, int K) {
    dim3 grid(N / BNt, M / BMt, 1);
    mma_gemm_kernel<false, true><<<grid, 256>>>(a.Ah, a.Al, a.Bh, a.Bl, a.bias,
                                                a.C, a.Ch, a.Cl, M, N, K, 0, 0, 0);
}

#define SYM(p, s) cudaGetSymbolAddress((void**)&p, s)

extern "C" void kernel_launch(void* const* d_in, const int* in_sizes, int n_in,
                              void* d_out, int out_size) {
    const float* x        = (const float*)d_in[0];
    const float* adj      = (const float*)d_in[1];
    const float* t_x      = (const float*)d_in[2];
    const float* t_adj    = (const float*)d_in[3];
    const float* tfidf    = (const float*)d_in[4];
    const float* gat_W    = (const float*)d_in[5];
    const float* gat_asrc = (const float*)d_in[6];
    const float* gat_adst = (const float*)d_in[7];
    const float* gat_fcW  = (const float*)d_in[8];
    const float* gat_fcb  = (const float*)d_in[9];
    const float* t_W      = (const float*)d_in[10];
    const float* t_asrc   = (const float*)d_in[11];
    const float* t_adst   = (const float*)d_in[12];
    const float* t_fcW    = (const float*)d_in[13];
    const float* t_fcb    = (const float*)d_in[14];
    const float* fus_W    = (const float*)d_in[15];
    const float* fus_b    = (const float*)d_in[16];
    const float* gc1_W    = (const float*)d_in[17];
    const float* gc2_W    = (const float*)d_in[18];
    const float* gc3_W    = (const float*)d_in[19];

    float* out    = (float*)d_out;
    float* mu     = out + (size_t)Nn * Nn;
    float* logvar = mu + (size_t)Nn * H2d;

    float *Wh_c, *Wh_t, *f_c, *g_c, *f_t, *g_t, *val_c, *val_t;
    float *concept, *ctext, *tmp1, *h1, *tmp2a, *tmp2b;
    int *nbr_c, *cnt_c, *nbr_t, *cnt_t;
    float *x_h, *x_l, *tx_h, *tx_l, *tf_h, *tf_l;
    float *gatW_h, *gatW_l, *tW_h, *tW_l, *fcWc_h, *fcWc_l, *fcWt_h, *fcWt_l;
    float *fusW_h, *fusW_l, *gc1W_h, *gc1W_l;
    float *hcatc_h, *hcatc_l, *hcatt_h, *hcatt_l, *gtext_h, *gtext_l;
    float *fused_h, *fused_l, *fusion_h, *fusion_l, *mu_h, *mu_l;
    SYM(Wh_c, g_Wh_c);  SYM(Wh_t, g_Wh_t);
    SYM(f_c, g_f_c);    SYM(g_c, g_g_c);   SYM(f_t, g_f_t);  SYM(g_t, g_g_t);
    SYM(nbr_c, g_nbr_c); SYM(val_c, g_val_c); SYM(cnt_c, g_cnt_c);
    SYM(nbr_t, g_nbr_t); SYM(val_t, g_val_t); SYM(cnt_t, g_cnt_t);
    SYM(concept, g_concept); SYM(ctext, g_ctext);
    SYM(tmp1, g_tmp1); SYM(h1, g_h1); SYM(tmp2a, g_tmp2a); SYM(tmp2b, g_tmp2b);
    SYM(x_h, g_x_h);   SYM(x_l, g_x_l);  SYM(tx_h, g_tx_h); SYM(tx_l, g_tx_l);
    SYM(tf_h, g_tf_h); SYM(tf_l, g_tf_l);
    SYM(gatW_h, g_gatW_h); SYM(gatW_l, g_gatW_l);
    SYM(tW_h, g_tW_h);     SYM(tW_l, g_tW_l);
    SYM(fcWc_h, g_fcWc_h); SYM(fcWc_l, g_fcWc_l);
    SYM(fcWt_h, g_fcWt_h); SYM(fcWt_l, g_fcWt_l);
    SYM(fusW_h, g_fusW_h); SYM(fusW_l, g_fusW_l);
    SYM(gc1W_h, g_gc1W_h); SYM(gc1W_l, g_gc1W_l);
    SYM(hcatc_h, g_hcatc_h); SYM(hcatc_l, g_hcatc_l);
    SYM(hcatt_h, g_hcatt_h); SYM(hcatt_l, g_hcatt_l);
    SYM(gtext_h, g_gtext_h); SYM(gtext_l, g_gtext_l);
    SYM(fused_h, g_fused_h); SYM(fused_l, g_fused_l);
    SYM(fusion_h, g_fusion_h); SYM(fusion_l, g_fusion_l);
    SYM(mu_h, g_mu_h); SYM(mu_l, g_mu_l);

    // 0) split all harness inputs into tf32 hi/lo planes (one launch)
    {
        SplitJobs9 jobs;
        jobs.j[0] = { x,       x_h,    x_l,    Nn * Dd / 4 };
        jobs.j[1] = { t_x,     tx_h,   tx_l,   Tt * Dd / 4 };
        jobs.j[2] = { tfidf,   tf_h,   tf_l,   Tt * Nn / 4 };
        jobs.j[3] = { gat_W,   gatW_h, gatW_l, NHd * Dd * Dd / 4 };
        jobs.j[4] = { t_W,     tW_h,   tW_l,   NHd * Dd * Dd / 4 };
        jobs.j[5] = { gat_fcW, fcWc_h, fcWc_l, NHd * Dd * Dd / 4 };
        jobs.j[6] = { t_fcW,   fcWt_h, fcWt_l, NHd * Dd * Dd / 4 };
        jobs.j[7] = { fus_W,   fusW_h, fusW_l, Dd * Dd / 4 };
        jobs.j[8] = { gc1_W,   gc1W_h, gc1W_l, Dd * H1d / 4 };
        split_all_kernel<<<dim3(160, 9), 256>>>(jobs);
    }

    // 1) adjacency -> CSR
    build_csr_kernel<<<Nn, 256>>>(adj, Nn, nbr_c, val_c, cnt_c);
    build_csr_kernel<<<Tt, 256>>>(t_adj, Tt, nbr_t, val_t, cnt_t);

    // 2) per-head Wh = x @ W[h]  (batched over heads, raw output)
    run_nn({x_h, x_l, gatW_h, gatW_l, nullptr, Wh_c, nullptr, nullptr},
           Nn, Dd, Dd, NHd, 0, (size_t)Dd * Dd, (size_t)Nn * Dd);
    run_nn({tx_h, tx_l, tW_h, tW_l, nullptr, Wh_t, nullptr, nullptr},
           Tt, Dd, Dd, NHd, 0, (size_t)Dd * Dd, (size_t)Tt * Dd);

    // 3) attention projections f,g
    fg_kernel<<<(NHd * Nn * 32 + 255) / 256, 256>>>(Wh_c, gat_asrc, gat_adst, f_c, g_c, Nn);
    fg_kernel<<<(NHd * Tt * 32 + 255) / 256, 256>>>(Wh_t, t_asrc, t_adst, f_t, g_t, Tt);

    // 4) sparse attention + aggregation + ELU -> hcat hi/lo planes
    gat_attn_warp_kernel<<<Nn * NHd / 8, 256>>>(Wh_c, f_c, g_c, nbr_c, cnt_c,
                                                hcatc_h, hcatc_l, Nn);
    gat_attn_warp_kernel<<<Tt * NHd / 8, 256>>>(Wh_t, f_t, g_t, nbr_t, cnt_t,
                                                hcatt_h, hcatt_l, Tt);

    // 5) output fc per graph
    run_nn({hcatc_h, hcatc_l, fcWc_h, fcWc_l, gat_fcb, concept, nullptr, nullptr},
           Nn, Dd, NHd * Dd);
    run_nn({hcatt_h, hcatt_l, fcWt_h, fcWt_l, t_fcb, nullptr, gtext_h, gtext_l},
           Tt, Dd, NHd * Dd);

    // 6) c_text = tfidf^T @ gat_text
    run_tn({tf_h, tf_l, gtext_h, gtext_l, nullptr, ctext, nullptr, nullptr},
           Nn, Dd, Tt);

    // 7) gated fusion + fc
    fuse_kernel<<<(Nn * Dd + 255) / 256, 256>>>(concept, ctext, fused_h, fused_l, Nn * Dd);
    run_nn({fused_h, fused_l, fusW_h, fusW_l, fus_b, nullptr, fusion_h, fusion_l},
           Nn, Dd, Dd);

    // 8) GCN encoder
    run_nn({fusion_h, fusion_l, gc1W_h, gc1W_l, nullptr, tmp1, nullptr, nullptr},
           Nn, H1d, Dd);
    spmm_kernel<<<Nn, H1d>>>(nbr_c, val_c, cnt_c, tmp1, h1, H1d, 1);

    gc23_kernel<<<Nn / 64, 256>>>(h1, gc2_W, gc3_W, tmp2a, tmp2b);
    spmm2_kernel<<<Nn, 64>>>(nbr_c, val_c, cnt_c, tmp2a, tmp2b, mu, logvar, mu_h, mu_l);

    // 9) recon = mu @ mu^T
    run_nt({mu_h, mu_l, mu_h, mu_l, nullptr, out, nullptr, nullptr}, Nn, Nn, H2d);
}